// round 1
// baseline (speedup 1.0000x reference)
#include <cuda_runtime.h>
#include <math.h>

// Problem dims (fixed by reference setup_inputs)
#define B_   32
#define S_   512
#define D_   768
#define M_   384
#define H_   8
#define DK_  96
#define BS_  (B_*S_)          // 16384 rows total
#define NM_  (BS_*M_)         // 6291456 elems of [BS,384]

// ---------------- static device scratch (no runtime alloc allowed) -------------
__device__ float g_Q    [BS_*D_];         // 50 MB
__device__ float g_K    [BS_*D_];         // 50 MB
__device__ float g_scores[67108864];      // 268 MB: [B,H,S,S]; later aliased for C11,C12,C21,C22
__device__ float g_adj  [B_*S_*S_];       // 33 MB  adj_ag
__device__ float g_AH1  [BS_*D_];         // scratch (768-wide max)
__device__ float g_AH2  [BS_*D_];
__device__ float g_Isem [NM_];
__device__ float g_Idep [NM_];
__device__ float g_Hout [NM_];
__device__ float g_Hl   [NM_];
__device__ float g_T    [BS_*32];
__device__ float g_h1   [NM_];
__device__ float g_h2   [NM_];
__device__ float g_n1   [NM_];
__device__ float g_n2   [NM_];
__device__ float g_rowloss[BS_];

// =============================================================================
// Generic fp32 SGEMM, NN: C[z] = act(A[z] @ B[z] + bias)
// 128x128 tile, BK=8, 256 threads, 8x8 microtile.
// Assumes: M % 128 == 0 (true for 16384 and 512), K % 8 == 0, lda/ldb/ldc % 4 == 0.
// N may be arbitrary (guarded) -- needed for fc1 (N=32).
// act: 0 none, 1 relu, 2 elu
// =============================================================================
__global__ __launch_bounds__(256)
void gemm_nn_kernel(const float* __restrict__ Abase, const float* __restrict__ Bbase,
                    const float* __restrict__ bias, float* __restrict__ Cbase,
                    int M, int N, int K, int lda, int ldb, int ldc,
                    long long sA, long long sB, long long sC, int act)
{
    const float* A  = Abase + (long long)blockIdx.z * sA;
    const float* Bm = Bbase + (long long)blockIdx.z * sB;
    float*       C  = Cbase + (long long)blockIdx.z * sC;
    int bm = blockIdx.y * 128;
    int bn = blockIdx.x * 128;

    __shared__ float As[8][128];
    __shared__ float Bs[8][128];

    int tid = threadIdx.x;
    int tx = tid & 15, ty = tid >> 4;

    float acc[8][8];
#pragma unroll
    for (int i = 0; i < 8; i++)
#pragma unroll
        for (int j = 0; j < 8; j++) acc[i][j] = 0.f;

    int arow = tid >> 1;            // 0..127
    int acol = (tid & 1) << 2;      // 0 or 4
    int brow = tid >> 5;            // 0..7
    int bcol = (tid & 31) << 2;     // 0..124

    for (int k0 = 0; k0 < K; k0 += 8) {
        float4 av = *reinterpret_cast<const float4*>(A + (long long)(bm + arow) * lda + (k0 + acol));
        As[acol + 0][arow] = av.x; As[acol + 1][arow] = av.y;
        As[acol + 2][arow] = av.z; As[acol + 3][arow] = av.w;

        int gc = bn + bcol;
        const float* bp = Bm + (long long)(k0 + brow) * ldb + gc;
        float4 bv;
        if (gc + 3 < N) {
            bv = *reinterpret_cast<const float4*>(bp);
        } else {
            bv.x = (gc + 0 < N) ? bp[0] : 0.f;
            bv.y = (gc + 1 < N) ? bp[1] : 0.f;
            bv.z = (gc + 2 < N) ? bp[2] : 0.f;
            bv.w = (gc + 3 < N) ? bp[3] : 0.f;
        }
        *reinterpret_cast<float4*>(&Bs[brow][bcol]) = bv;
        __syncthreads();

#pragma unroll
        for (int kk = 0; kk < 8; kk++) {
            float a[8], b[8];
            *reinterpret_cast<float4*>(&a[0]) = *reinterpret_cast<const float4*>(&As[kk][ty << 3]);
            *reinterpret_cast<float4*>(&a[4]) = *reinterpret_cast<const float4*>(&As[kk][(ty << 3) + 4]);
            *reinterpret_cast<float4*>(&b[0]) = *reinterpret_cast<const float4*>(&Bs[kk][tx << 3]);
            *reinterpret_cast<float4*>(&b[4]) = *reinterpret_cast<const float4*>(&Bs[kk][(tx << 3) + 4]);
#pragma unroll
            for (int i = 0; i < 8; i++)
#pragma unroll
                for (int j = 0; j < 8; j++)
                    acc[i][j] = fmaf(a[i], b[j], acc[i][j]);
        }
        __syncthreads();
    }

#pragma unroll
    for (int i = 0; i < 8; i++) {
        int r = bm + (ty << 3) + i;
#pragma unroll
        for (int j = 0; j < 8; j++) {
            int c = bn + (tx << 3) + j;
            if (c < N) {
                float v = acc[i][j];
                if (bias) v += bias[c];
                if (act == 1)      v = fmaxf(v, 0.f);
                else if (act == 2) v = v > 0.f ? v : (expf(v) - 1.f);
                C[(long long)r * ldc + c] = v;
            }
        }
    }
}

// =============================================================================
// Generic fp32 SGEMM, NT: C[z][s,t] = alpha * sum_k A[z][s,k]*B[z][t,k]
// Batch index z = zo*nInner + zi with separate strides (used for per-head Q@K^T).
// Assumes M % 128 == 0, N % 128 == 0, K % 8 == 0 (all uses: 512x512, K in {96,384}).
// =============================================================================
__global__ __launch_bounds__(256)
void gemm_nt_kernel(const float* __restrict__ Abase, const float* __restrict__ Bbase,
                    float* __restrict__ Cbase,
                    int M, int N, int K, int lda, int ldb, int ldc,
                    int nInner, long long sAo, long long sAi,
                    long long sBo, long long sBi, long long sC, float alpha)
{
    int z = blockIdx.z;
    int zo = z / nInner, zi = z - zo * nInner;
    const float* A  = Abase + (long long)zo * sAo + (long long)zi * sAi;
    const float* Bm = Bbase + (long long)zo * sBo + (long long)zi * sBi;
    float*       C  = Cbase + (long long)z * sC;

    int bm = blockIdx.y * 128;
    int bn = blockIdx.x * 128;

    __shared__ float As[8][128];
    __shared__ float Bs[8][128];

    int tid = threadIdx.x;
    int tx = tid & 15, ty = tid >> 4;

    float acc[8][8];
#pragma unroll
    for (int i = 0; i < 8; i++)
#pragma unroll
        for (int j = 0; j < 8; j++) acc[i][j] = 0.f;

    int arow = tid >> 1;
    int acol = (tid & 1) << 2;

    for (int k0 = 0; k0 < K; k0 += 8) {
        float4 av = *reinterpret_cast<const float4*>(A + (long long)(bm + arow) * lda + (k0 + acol));
        As[acol + 0][arow] = av.x; As[acol + 1][arow] = av.y;
        As[acol + 2][arow] = av.z; As[acol + 3][arow] = av.w;

        float4 bv = *reinterpret_cast<const float4*>(Bm + (long long)(bn + arow) * ldb + (k0 + acol));
        Bs[acol + 0][arow] = bv.x; Bs[acol + 1][arow] = bv.y;
        Bs[acol + 2][arow] = bv.z; Bs[acol + 3][arow] = bv.w;
        __syncthreads();

#pragma unroll
        for (int kk = 0; kk < 8; kk++) {
            float a[8], b[8];
            *reinterpret_cast<float4*>(&a[0]) = *reinterpret_cast<const float4*>(&As[kk][ty << 3]);
            *reinterpret_cast<float4*>(&a[4]) = *reinterpret_cast<const float4*>(&As[kk][(ty << 3) + 4]);
            *reinterpret_cast<float4*>(&b[0]) = *reinterpret_cast<const float4*>(&Bs[kk][tx << 3]);
            *reinterpret_cast<float4*>(&b[4]) = *reinterpret_cast<const float4*>(&Bs[kk][(tx << 3) + 4]);
#pragma unroll
            for (int i = 0; i < 8; i++)
#pragma unroll
                for (int j = 0; j < 8; j++)
                    acc[i][j] = fmaf(a[i], b[j], acc[i][j]);
        }
        __syncthreads();
    }

#pragma unroll
    for (int i = 0; i < 8; i++) {
        int r = bm + (ty << 3) + i;
#pragma unroll
        for (int j = 0; j < 8; j++) {
            int c = bn + (tx << 3) + j;
            C[(long long)r * ldc + c] = acc[i][j] * alpha;
        }
    }
}

// =============================================================================
// Masked softmax over keys, mean over 8 heads, diag->1, row-mask. block=(512), grid=(S,B)
// adj[b,s,t] = attn_mask[b,s] * ( s==t ? 1 : mean_h softmax_t(masked scores)[t] )
// =============================================================================
__global__ void softmax_mean_kernel(const float* __restrict__ scores,
                                    const int* __restrict__ attn_mask,
                                    float* __restrict__ adj)
{
    int s = blockIdx.x, b = blockIdx.y;
    int t = threadIdx.x;                  // 0..511
    int lane = t & 31, wid = t >> 5;      // 16 warps
    __shared__ float red[16];
    __shared__ float bval;

    float colmask = (float)attn_mask[b * S_ + t];
    float acc = 0.f;

    for (int h = 0; h < H_; h++) {
        const float* row = scores + ((((long long)b * H_ + h) * S_ + s) << 9);
        float v = row[t];
        if (colmask == 0.f) v = -10000.f;

        // block max
        float mx = v;
#pragma unroll
        for (int o = 16; o > 0; o >>= 1) mx = fmaxf(mx, __shfl_xor_sync(0xffffffffu, mx, o));
        if (lane == 0) red[wid] = mx;
        __syncthreads();
        if (wid == 0) {
            float x = (lane < 16) ? red[lane] : -INFINITY;
#pragma unroll
            for (int o = 16; o > 0; o >>= 1) x = fmaxf(x, __shfl_xor_sync(0xffffffffu, x, o));
            if (lane == 0) bval = x;
        }
        __syncthreads();
        mx = bval;

        float e = expf(v - mx);
        float sm = e;
#pragma unroll
        for (int o = 16; o > 0; o >>= 1) sm += __shfl_xor_sync(0xffffffffu, sm, o);
        __syncthreads();                   // red no longer needed for max
        if (lane == 0) red[wid] = sm;
        __syncthreads();
        if (wid == 0) {
            float x = (lane < 16) ? red[lane] : 0.f;
#pragma unroll
            for (int o = 16; o > 0; o >>= 1) x += __shfl_xor_sync(0xffffffffu, x, o);
            if (lane == 0) bval = x;
        }
        __syncthreads();
        acc += e / bval;
        __syncthreads();                   // bval/red stable before next head
    }

    float val = (t == s) ? 1.f : acc * 0.125f;
    val *= (float)attn_mask[b * S_ + s];   // row mask
    adj[(((long long)b * S_ + s) << 9) + t] = val;
}

// I_com = (1 - 0.6*sigmoid(I_dep))*I_sem + 0.6*sigmoid(I_dep)*I_dep   (in-place into d)
__global__ void combine_kernel(const float* __restrict__ s, float* __restrict__ d, int n)
{
    int i = blockIdx.x * blockDim.x + threadIdx.x;
    int stride = gridDim.x * blockDim.x;
    for (; i < n; i += stride) {
        float dv = d[i], sv = s[i];
        float g = 1.f / (1.f + expf(-dv));
        float dg = 0.6f * g;
        d[i] = (1.f - dg) * sv + dg * dv;
    }
}

// H = sigmoid(H)*Hout + (1-sigmoid(H))*H   (in-place)
__global__ void gate_kernel(float* __restrict__ h, const float* __restrict__ hout, int n)
{
    int i = blockIdx.x * blockDim.x + threadIdx.x;
    int stride = gridDim.x * blockDim.x;
    for (; i < n; i += stride) {
        float hv = h[i];
        float g = 1.f / (1.f + expf(-hv));
        h[i] = g * hout[i] + (1.f - g) * hv;
    }
}

// Row L2-normalize: out = z / max(||z||, 1e-12). One warp per row.
__global__ void normalize_kernel(const float* __restrict__ z, float* __restrict__ out,
                                 int rows, int cols)
{
    int gw = (blockIdx.x * blockDim.x + threadIdx.x) >> 5;
    int lane = threadIdx.x & 31;
    int nw = (gridDim.x * blockDim.x) >> 5;
    for (int r = gw; r < rows; r += nw) {
        const float* zr = z + (long long)r * cols;
        float ss = 0.f;
        for (int c = lane; c < cols; c += 32) { float v = zr[c]; ss += v * v; }
#pragma unroll
        for (int o = 16; o > 0; o >>= 1) ss += __shfl_xor_sync(0xffffffffu, ss, o);
        float inv = 1.f / fmaxf(sqrtf(ss), 1e-12f);
        float* orow = out + (long long)r * cols;
        for (int c = lane; c < cols; c += 32) orow[c] = zr[c] * inv;
    }
}

// =============================================================================
// Scope contrastive loss per (b,s). Uses identity:
//   sim(z*rowmask, z2*colmask)[s,t] = rowmask[s]*colmask[t]*C[s,t]
// l1 uses C11 (refl) + C12 (between); l2 uses C22 + C21.
// block=(512) one t each, grid=(S,B).
// =============================================================================
__global__ void loss_kernel(const float* __restrict__ C11, const float* __restrict__ C12,
                            const float* __restrict__ C21, const float* __restrict__ C22,
                            const int* __restrict__ s_mask, const int* __restrict__ a_mask,
                            float* __restrict__ rowloss)
{
    int s = blockIdx.x, b = blockIdx.y;
    int t = threadIdx.x;
    int lane = t & 31, wid = t >> 5;
    __shared__ float red8[8][16];
    __shared__ float Ssh[8];

    const float it = 1.f / 0.07f;
    long long base = (((long long)b * S_ + s) << 9);
    long long diag = base + s;

    float a   = (float)a_mask[b * S_ + s];
    float sms = (float)s_mask[b * S_ + s];
    float smt = (float)s_mask[b * S_ + t];

    float d11 = C11[diag], d12 = C12[diag], d21 = C21[diag], d22 = C22[diag];
    float dw1 = a * sms * d12;
    float dw2 = a * sms * d21;

    float c11 = C11[base + t], c12 = C12[base + t];
    float c21 = C21[base + t], c22 = C22[base + t];

    float vals[8];
    vals[0] = expf(a * c11 * it);               // m_refl      (l1)
    vals[1] = expf(a * c12 * it);               // m_between   (l1)
    vals[2] = expf(a * smt * c11 * it);         // as_refl     (l1)
    vals[3] = expf(a * smt * c12 * dw1 * it);   // weighted    (l1)
    vals[4] = expf(a * c22 * it);               // m_refl      (l2)
    vals[5] = expf(a * c21 * it);               // m_between   (l2)
    vals[6] = expf(a * smt * c22 * it);         // as_refl     (l2)
    vals[7] = expf(a * smt * c21 * dw2 * it);   // weighted    (l2)

#pragma unroll
    for (int k = 0; k < 8; k++) {
        float v = vals[k];
#pragma unroll
        for (int o = 16; o > 0; o >>= 1) v += __shfl_xor_sync(0xffffffffu, v, o);
        if (lane == 0) red8[k][wid] = v;
    }
    __syncthreads();
    if (t < 8) {
        float x = 0.f;
        for (int w2 = 0; w2 < 16; w2++) x += red8[t][w2];
        Ssh[t] = x;
    }
    __syncthreads();

    if (t == 0) {
        float pos1 = expf(a * sms * d12 * it)
                   + (Ssh[2] - expf(a * sms * d11 * it))
                   + (Ssh[3] - expf(dw1 * dw1 * it));
        float alle1 = Ssh[0] + Ssh[1] - expf(a * d11 * it);
        float l1v = -logf(pos1 / alle1);

        float pos2 = expf(a * sms * d21 * it)
                   + (Ssh[6] - expf(a * sms * d22 * it))
                   + (Ssh[7] - expf(dw2 * dw2 * it));
        float alle2 = Ssh[4] + Ssh[5] - expf(a * d22 * it);
        float l2v = -logf(pos2 / alle2);

        rowloss[b * S_ + s] = 0.5f * (l1v + l2v);
    }
}

__global__ void final_reduce_kernel(const float* __restrict__ rl, float* __restrict__ out)
{
    __shared__ float red[32];
    int tid = threadIdx.x;                 // 1024 threads
    float s = 0.f;
    for (int i = tid; i < BS_; i += 1024) s += rl[i];
#pragma unroll
    for (int o = 16; o > 0; o >>= 1) s += __shfl_xor_sync(0xffffffffu, s, o);
    if ((tid & 31) == 0) red[tid >> 5] = s;
    __syncthreads();
    if (tid < 32) {
        float x = red[tid];
#pragma unroll
        for (int o = 16; o > 0; o >>= 1) x += __shfl_xor_sync(0xffffffffu, x, o);
        if (tid == 0) out[0] = x / (float)BS_;
    }
}

// =============================================================================
extern "C" void kernel_launch(void* const* d_in, const int* in_sizes, int n_in,
                              void* d_out, int out_size)
{
    const float* X     = (const float*)d_in[0];
    const float* adjm  = (const float*)d_in[1];
    const int*   amask = (const int*)d_in[2];   // attn_mask [B,1,S]
    const int*   smsk  = (const int*)d_in[3];   // s_mask
    const int*   amsk  = (const int*)d_in[4];   // a_mask
    const float* Wq    = (const float*)d_in[5];
    const float* bq    = (const float*)d_in[6];
    const float* Wk    = (const float*)d_in[7];
    const float* bk    = (const float*)d_in[8];
    const float* semW0 = (const float*)d_in[9];
    const float* semb0 = (const float*)d_in[10];
    const float* semW1 = (const float*)d_in[11];
    const float* semb1 = (const float*)d_in[12];
    const float* depW0 = (const float*)d_in[13];
    const float* depb0 = (const float*)d_in[14];
    const float* depW1 = (const float*)d_in[15];
    const float* depb1 = (const float*)d_in[16];
    const float* fc1W  = (const float*)d_in[17];
    const float* fc1b  = (const float*)d_in[18];
    const float* fc2W  = (const float*)d_in[19];
    const float* fc2b  = (const float*)d_in[20];
    const float* fc3W  = (const float*)d_in[21];
    const float* fc3b  = (const float*)d_in[22];
    const float* fc4W  = (const float*)d_in[23];
    const float* fc4b  = (const float*)d_in[24];
    float* out = (float*)d_out;

    float *pQ, *pK, *pS, *pAdj, *pAH1, *pAH2, *pIsem, *pIdep, *pHout, *pHl, *pT,
          *ph1, *ph2, *pn1, *pn2, *pRL;
    cudaGetSymbolAddress((void**)&pQ, g_Q);
    cudaGetSymbolAddress((void**)&pK, g_K);
    cudaGetSymbolAddress((void**)&pS, g_scores);
    cudaGetSymbolAddress((void**)&pAdj, g_adj);
    cudaGetSymbolAddress((void**)&pAH1, g_AH1);
    cudaGetSymbolAddress((void**)&pAH2, g_AH2);
    cudaGetSymbolAddress((void**)&pIsem, g_Isem);
    cudaGetSymbolAddress((void**)&pIdep, g_Idep);
    cudaGetSymbolAddress((void**)&pHout, g_Hout);
    cudaGetSymbolAddress((void**)&pHl, g_Hl);
    cudaGetSymbolAddress((void**)&pT, g_T);
    cudaGetSymbolAddress((void**)&ph1, g_h1);
    cudaGetSymbolAddress((void**)&ph2, g_h2);
    cudaGetSymbolAddress((void**)&pn1, g_n1);
    cudaGetSymbolAddress((void**)&pn2, g_n2);
    cudaGetSymbolAddress((void**)&pRL, g_rowloss);

    // C-matrix aliases inside the big scores buffer
    float* C11 = pS;
    float* C12 = pS + (long long)B_ * S_ * S_;
    float* C21 = pS + 2LL * B_ * S_ * S_;
    float* C22 = pS + 3LL * B_ * S_ * S_;

    dim3 blk(256);
    const long long SS = (long long)S_ * S_;       // 262144
    const long long SD = (long long)S_ * D_;       // 393216
    const long long SM = (long long)S_ * M_;       // 196608

    // ---- 1,2: Q/K projections ----
    gemm_nn_kernel<<<dim3(6, 128, 1), blk>>>(X, Wq, bq, pQ, BS_, D_, D_, D_, D_, D_, 0, 0, 0, 0);
    gemm_nn_kernel<<<dim3(6, 128, 1), blk>>>(X, Wk, bk, pK, BS_, D_, D_, D_, D_, D_, 0, 0, 0, 0);

    // ---- 3: per-head scores = Q_bh @ K_bh^T / sqrt(dk) ----
    float alpha = 1.0f / sqrtf((float)DK_);
    gemm_nt_kernel<<<dim3(4, 4, B_ * H_), blk>>>(pQ, pK, pS, S_, S_, DK_, D_, D_, S_,
                                                 H_, SD, DK_, SD, DK_, SS, alpha);

    // ---- 4: masked softmax + head mean + diag/row-mask -> adj_ag ----
    softmax_mean_kernel<<<dim3(S_, B_), 512>>>(pS, amask, pAdj);

    // ---- Layer 0 ----
    gemm_nn_kernel<<<dim3(6, 4, B_), blk>>>(pAdj, X, nullptr, pAH1, S_, D_, S_, S_, D_, D_, SS, SD, SD, 0);
    gemm_nn_kernel<<<dim3(3, 128, 1), blk>>>(pAH1, semW0, semb0, pIsem, BS_, M_, D_, D_, M_, M_, 0, 0, 0, 0);
    gemm_nn_kernel<<<dim3(6, 4, B_), blk>>>(adjm, X, nullptr, pAH2, S_, D_, S_, S_, D_, D_, SS, SD, SD, 0);
    gemm_nn_kernel<<<dim3(3, 128, 1), blk>>>(pAH2, depW0, depb0, pIdep, BS_, M_, D_, D_, M_, M_, 0, 0, 0, 0);
    combine_kernel<<<4096, 256>>>(pIsem, pIdep, NM_);
    gemm_nn_kernel<<<dim3(3, 128, 1), blk>>>(pIdep, fc3W, fc3b, pHout, BS_, M_, M_, M_, M_, M_, 0, 0, 0, 1);
    gemm_nn_kernel<<<dim3(3, 128, 1), blk>>>(X, fc4W, fc4b, pHl, BS_, M_, D_, D_, M_, M_, 0, 0, 0, 0);
    gate_kernel<<<4096, 256>>>(pHl, pHout, NM_);

    // ---- Layer 1 ----
    gemm_nn_kernel<<<dim3(3, 4, B_), blk>>>(pAdj, pHl, nullptr, pAH1, S_, M_, S_, S_, M_, M_, SS, SM, SM, 0);
    gemm_nn_kernel<<<dim3(3, 128, 1), blk>>>(pAH1, semW1, semb1, pIsem, BS_, M_, M_, M_, M_, M_, 0, 0, 0, 0);
    gemm_nn_kernel<<<dim3(3, 4, B_), blk>>>(adjm, pHl, nullptr, pAH2, S_, M_, S_, S_, M_, M_, SS, SM, SM, 0);
    gemm_nn_kernel<<<dim3(3, 128, 1), blk>>>(pAH2, depW1, depb1, pIdep, BS_, M_, M_, M_, M_, M_, 0, 0, 0, 0);
    combine_kernel<<<4096, 256>>>(pIsem, pIdep, NM_);
    gemm_nn_kernel<<<dim3(3, 128, 1), blk>>>(pIdep, fc3W, fc3b, pHout, BS_, M_, M_, M_, M_, M_, 0, 0, 0, 1);
    gate_kernel<<<4096, 256>>>(pHl, pHout, NM_);   // final H_l

    // ---- projection head: h1 = proj(H_l), h2 = proj(I_sem) ----
    gemm_nn_kernel<<<dim3(1, 128, 1), blk>>>(pHl, fc1W, fc1b, pT, BS_, 32, M_, M_, 32, 32, 0, 0, 0, 2);
    gemm_nn_kernel<<<dim3(3, 128, 1), blk>>>(pT, fc2W, fc2b, ph1, BS_, M_, 32, 32, M_, M_, 0, 0, 0, 0);
    gemm_nn_kernel<<<dim3(1, 128, 1), blk>>>(pIsem, fc1W, fc1b, pT, BS_, 32, M_, M_, 32, 32, 0, 0, 0, 2);
    gemm_nn_kernel<<<dim3(3, 128, 1), blk>>>(pT, fc2W, fc2b, ph2, BS_, M_, 32, 32, M_, M_, 0, 0, 0, 0);

    // ---- normalize rows ----
    normalize_kernel<<<2048, 256>>>(ph1, pn1, BS_, M_);
    normalize_kernel<<<2048, 256>>>(ph2, pn2, BS_, M_);

    // ---- cosine similarity matrices (batched NT, K=384) ----
    gemm_nt_kernel<<<dim3(4, 4, B_), blk>>>(pn1, pn1, C11, S_, S_, M_, M_, M_, S_, 1, SM, 0, SM, 0, SS, 1.f);
    gemm_nt_kernel<<<dim3(4, 4, B_), blk>>>(pn1, pn2, C12, S_, S_, M_, M_, M_, S_, 1, SM, 0, SM, 0, SS, 1.f);
    gemm_nt_kernel<<<dim3(4, 4, B_), blk>>>(pn2, pn1, C21, S_, S_, M_, M_, M_, S_, 1, SM, 0, SM, 0, SS, 1.f);
    gemm_nt_kernel<<<dim3(4, 4, B_), blk>>>(pn2, pn2, C22, S_, S_, M_, M_, M_, S_, 1, SM, 0, SM, 0, SS, 1.f);

    // ---- loss ----
    loss_kernel<<<dim3(S_, B_), 512>>>(C11, C12, C21, C22, smsk, amsk, pRL);
    final_reduce_kernel<<<1, 1024>>>(pRL, out);
}

// round 3
// speedup vs baseline: 3.0979x; 3.0979x over previous
#include <cuda_runtime.h>
#include <math.h>
#include <stdint.h>

// Problem dims (fixed by reference setup_inputs)
#define B_   32
#define S_   512
#define D_   768
#define M_   384
#define H_   8
#define DK_  96
#define BS_  (B_*S_)          // 16384 rows total
#define NM_  (BS_*M_)         // 6291456 elems of [BS,384]

// ---------------- static device scratch (no runtime alloc allowed) -------------
__device__ float g_Q    [BS_*D_];
__device__ float g_K    [BS_*D_];
__device__ float g_scores[67108864];      // [B,H,S,S]; later aliased for C11,C12,C21,C22
__device__ float g_adj  [B_*S_*S_];
__device__ float g_AH1  [BS_*D_];
__device__ float g_AH2  [BS_*D_];
__device__ float g_Isem [NM_];
__device__ float g_Idep [NM_];
__device__ float g_Hout [NM_];
__device__ float g_Hl   [NM_];
__device__ float g_T    [BS_*32];
__device__ float g_h1   [NM_];
__device__ float g_h2   [NM_];
__device__ float g_n1   [NM_];
__device__ float g_n2   [NM_];
__device__ float g_rowloss[BS_];

// round-to-nearest fp32 -> tf32 (keeps bit pattern in a float)
__device__ __forceinline__ float tf32r(float x) {
    uint32_t u;
    asm("cvt.rna.tf32.f32 %0, %1;" : "=r"(u) : "f"(x));
    return __uint_as_float(u);
}

// =============================================================================
// TF32 tensor-core GEMM (mma.sync.m16n8k8), fp32 accumulate.
//   C[z] = act(alpha * A[z] @ op(B[z]) + bias)
// TRANSB=false: B is [K][N] row-major.  TRANSB=true: B is [N][K] row-major (NT).
// Tile 128x128x16, double-buffered smem, 256 threads (8 warps, 2x4).
// Requirements: M%128==0, K%16==0, lda/ldb multiples of 4, A/B 16B-aligned rows.
// N arbitrary for NN (guarded); NT requires N%128==0 (all NT uses are 512).
// Batch z = zo*nInner + zi with independent A/B strides.
// act: 0 none, 1 relu, 2 elu
// =============================================================================
template<bool TRANSB>
__global__ __launch_bounds__(256)
void gemm_tf32_kernel(const float* __restrict__ Abase, const float* __restrict__ Bbase,
                      const float* __restrict__ bias, float* __restrict__ Cbase,
                      int M, int N, int K, int lda, int ldb, int ldc,
                      int nInner, long long sAo, long long sAi,
                      long long sBo, long long sBi, long long sC,
                      float alpha, int act)
{
    int z  = blockIdx.z;
    int zo = z / nInner, zi = z - zo * nInner;
    const float* A  = Abase + (long long)zo * sAo + (long long)zi * sAi;
    const float* Bm = Bbase + (long long)zo * sBo + (long long)zi * sBi;
    float*       C  = Cbase + (long long)z * sC;
    int bm = blockIdx.y * 128;
    int bn = blockIdx.x * 128;

    // As: [128][20] (16 used + 4 pad -> 5x16B stride, conflict-free ldmatrix)
    // Bs: [16][136] (128 used + 8 pad -> conflict-free B-frag LDS)
    __shared__ __align__(16) float As[2][128 * 20];
    __shared__ __align__(16) float Bs[2][16 * 136];

    int tid  = threadIdx.x;
    int lane = tid & 31;
    int wid  = tid >> 5;
    int wm   = wid >> 2;      // 0..1  (M dir, 64 rows each)
    int wn   = wid & 3;       // 0..3  (N dir, 32 cols each)

    float acc[4][4][4];
#pragma unroll
    for (int i = 0; i < 4; i++)
#pragma unroll
        for (int j = 0; j < 4; j++)
#pragma unroll
            for (int r = 0; r < 4; r++) acc[i][j][r] = 0.f;

    // ---- gmem load (into regs) ----
    auto gload = [&](int k0, float4& a0, float4& a1, float4& b0, float4& b1) {
        int ar = tid >> 2, ak = (tid & 3) << 2;
        a0 = *reinterpret_cast<const float4*>(A + (long long)(bm + ar)      * lda + k0 + ak);
        a1 = *reinterpret_cast<const float4*>(A + (long long)(bm + ar + 64) * lda + k0 + ak);
        if (TRANSB) {
            int n = tid >> 2, kc = (tid & 3) << 2;
            b0 = *reinterpret_cast<const float4*>(Bm + (long long)(bn + n)      * ldb + k0 + kc);
            b1 = *reinterpret_cast<const float4*>(Bm + (long long)(bn + n + 64) * ldb + k0 + kc);
        } else {
            int br = tid >> 5, bc = (tid & 31) << 2;
            int gc = bn + bc;
            const float* p0 = Bm + (long long)(k0 + br)     * ldb + gc;
            const float* p1 = Bm + (long long)(k0 + br + 8) * ldb + gc;
            if (gc + 3 < N) {
                b0 = *reinterpret_cast<const float4*>(p0);
                b1 = *reinterpret_cast<const float4*>(p1);
            } else {
                b0.x = (gc + 0 < N) ? p0[0] : 0.f; b0.y = (gc + 1 < N) ? p0[1] : 0.f;
                b0.z = (gc + 2 < N) ? p0[2] : 0.f; b0.w = (gc + 3 < N) ? p0[3] : 0.f;
                b1.x = (gc + 0 < N) ? p1[0] : 0.f; b1.y = (gc + 1 < N) ? p1[1] : 0.f;
                b1.z = (gc + 2 < N) ? p1[2] : 0.f; b1.w = (gc + 3 < N) ? p1[3] : 0.f;
            }
        }
    };

    // ---- regs -> smem (with tf32 rounding) ----
    auto sstore = [&](int buf, float4 a0, float4 a1, float4 b0, float4 b1) {
        int ar = tid >> 2, ak = (tid & 3) << 2;
        float* ap0 = &As[buf][ar * 20 + ak];
        ap0[0] = tf32r(a0.x); ap0[1] = tf32r(a0.y); ap0[2] = tf32r(a0.z); ap0[3] = tf32r(a0.w);
        float* ap1 = &As[buf][(ar + 64) * 20 + ak];
        ap1[0] = tf32r(a1.x); ap1[1] = tf32r(a1.y); ap1[2] = tf32r(a1.z); ap1[3] = tf32r(a1.w);
        if (TRANSB) {
            int n = tid >> 2, kc = (tid & 3) << 2;
            Bs[buf][(kc + 0) * 136 + n] = tf32r(b0.x);
            Bs[buf][(kc + 1) * 136 + n] = tf32r(b0.y);
            Bs[buf][(kc + 2) * 136 + n] = tf32r(b0.z);
            Bs[buf][(kc + 3) * 136 + n] = tf32r(b0.w);
            Bs[buf][(kc + 0) * 136 + n + 64] = tf32r(b1.x);
            Bs[buf][(kc + 1) * 136 + n + 64] = tf32r(b1.y);
            Bs[buf][(kc + 2) * 136 + n + 64] = tf32r(b1.z);
            Bs[buf][(kc + 3) * 136 + n + 64] = tf32r(b1.w);
        } else {
            int br = tid >> 5, bc = (tid & 31) << 2;
            float* bp0 = &Bs[buf][br * 136 + bc];
            bp0[0] = tf32r(b0.x); bp0[1] = tf32r(b0.y); bp0[2] = tf32r(b0.z); bp0[3] = tf32r(b0.w);
            float* bp1 = &Bs[buf][(br + 8) * 136 + bc];
            bp1[0] = tf32r(b1.x); bp1[1] = tf32r(b1.y); bp1[2] = tf32r(b1.z); bp1[3] = tf32r(b1.w);
        }
    };

    // ---- tensor-core compute on one smem stage ----
    auto compute = [&](int buf) {
        uint32_t asb = (uint32_t)__cvta_generic_to_shared(&As[buf][0]);
#pragma unroll
        for (int ks = 0; ks < 16; ks += 8) {
            uint32_t a[4][4];
#pragma unroll
            for (int mi = 0; mi < 4; mi++) {
                int row = wm * 64 + mi * 16 + (lane & 15);
                uint32_t addr = asb + (uint32_t)((row * 20 + ks + ((lane >> 4) << 2)) * 4);
                asm volatile("ldmatrix.sync.aligned.m8n8.x4.shared.b16 {%0,%1,%2,%3}, [%4];"
                             : "=r"(a[mi][0]), "=r"(a[mi][1]), "=r"(a[mi][2]), "=r"(a[mi][3])
                             : "r"(addr));
            }
            uint32_t bf[4][2];
#pragma unroll
            for (int ni = 0; ni < 4; ni++) {
                int coln = wn * 32 + ni * 8 + (lane >> 2);
                bf[ni][0] = __float_as_uint(Bs[buf][(ks + (lane & 3))     * 136 + coln]);
                bf[ni][1] = __float_as_uint(Bs[buf][(ks + (lane & 3) + 4) * 136 + coln]);
            }
#pragma unroll
            for (int mi = 0; mi < 4; mi++)
#pragma unroll
                for (int ni = 0; ni < 4; ni++) {
                    asm volatile(
                        "mma.sync.aligned.m16n8k8.row.col.f32.tf32.tf32.f32 "
                        "{%0,%1,%2,%3}, {%4,%5,%6,%7}, {%8,%9}, {%0,%1,%2,%3};"
                        : "+f"(acc[mi][ni][0]), "+f"(acc[mi][ni][1]),
                          "+f"(acc[mi][ni][2]), "+f"(acc[mi][ni][3])
                        : "r"(a[mi][0]), "r"(a[mi][1]), "r"(a[mi][2]), "r"(a[mi][3]),
                          "r"(bf[ni][0]), "r"(bf[ni][1]));
                }
        }
    };

    // ---- mainloop (double buffered) ----
    int KT = K >> 4;
    {
        float4 a0, a1, b0, b1;
        gload(0, a0, a1, b0, b1);
        sstore(0, a0, a1, b0, b1);
    }
    __syncthreads();
    for (int kt = 0; kt < KT; kt++) {
        int cur = kt & 1;
        float4 a0, a1, b0, b1;
        bool hn = (kt + 1 < KT);
        if (hn) gload((kt + 1) << 4, a0, a1, b0, b1);
        compute(cur);
        if (hn) sstore(cur ^ 1, a0, a1, b0, b1);
        __syncthreads();
    }

    // ---- epilogue ----
    int g = lane >> 2, q = lane & 3;
#pragma unroll
    for (int mi = 0; mi < 4; mi++) {
#pragma unroll
        for (int ni = 0; ni < 4; ni++) {
            int col = bn + wn * 32 + ni * 8 + 2 * q;
            if (col >= N) continue;
            float bb0 = bias ? bias[col]     : 0.f;
            float bb1 = bias ? bias[col + 1] : 0.f;
#pragma unroll
            for (int half = 0; half < 2; half++) {
                int r = bm + wm * 64 + mi * 16 + g + half * 8;
                float v0 = acc[mi][ni][half * 2 + 0] * alpha + bb0;
                float v1 = acc[mi][ni][half * 2 + 1] * alpha + bb1;
                if (act == 1) { v0 = fmaxf(v0, 0.f); v1 = fmaxf(v1, 0.f); }
                else if (act == 2) {
                    v0 = v0 > 0.f ? v0 : (expf(v0) - 1.f);
                    v1 = v1 > 0.f ? v1 : (expf(v1) - 1.f);
                }
                float2 o; o.x = v0; o.y = v1;
                *reinterpret_cast<float2*>(&C[(long long)r * ldc + col]) = o;
            }
        }
    }
}

// =============================================================================
// Masked softmax over keys + mean over 8 heads + diag->1 + row mask.
// One warp per head (8 warps = 256 threads); full-row reductions are pure
// warp shuffles. grid=(S,B).
// =============================================================================
__global__ void softmax_mean_kernel(const float* __restrict__ scores,
                                    const int* __restrict__ attn_mask,
                                    float* __restrict__ adj)
{
    int s = blockIdx.x, b = blockIdx.y;
    int tid = threadIdx.x;
    int lane = tid & 31, h = tid >> 5;    // warp = head
    __shared__ float accs[512];

    accs[tid] = 0.f; accs[tid + 256] = 0.f;
    __syncthreads();

    const float* row = scores + ((((long long)b * H_ + h) * S_ + s) << 9);
    const int* cm = attn_mask + b * S_;

    float v[16];
    float mx = -INFINITY;
#pragma unroll
    for (int j = 0; j < 16; j++) {
        int c = lane + (j << 5);
        float x = row[c];
        if (cm[c] == 0) x = -10000.f;
        v[j] = x;
        mx = fmaxf(mx, x);
    }
#pragma unroll
    for (int o = 16; o > 0; o >>= 1) mx = fmaxf(mx, __shfl_xor_sync(0xffffffffu, mx, o));

    float sum = 0.f;
#pragma unroll
    for (int j = 0; j < 16; j++) { v[j] = expf(v[j] - mx); sum += v[j]; }
#pragma unroll
    for (int o = 16; o > 0; o >>= 1) sum += __shfl_xor_sync(0xffffffffu, sum, o);
    float inv = 1.f / sum;

#pragma unroll
    for (int j = 0; j < 16; j++) atomicAdd(&accs[lane + (j << 5)], v[j] * inv);
    __syncthreads();

    float rmask = (float)attn_mask[b * S_ + s];
    long long obase = (((long long)b * S_ + s) << 9);
#pragma unroll
    for (int k = 0; k < 2; k++) {
        int c = tid + (k << 8);
        float val = (c == s) ? 1.f : accs[c] * 0.125f;
        adj[obase + c] = val * rmask;
    }
}

// I_com = (1 - 0.6*sigmoid(I_dep))*I_sem + 0.6*sigmoid(I_dep)*I_dep   (in-place into d)
__global__ void combine_kernel(const float* __restrict__ s, float* __restrict__ d, int n)
{
    int i = blockIdx.x * blockDim.x + threadIdx.x;
    int stride = gridDim.x * blockDim.x;
    for (; i < n; i += stride) {
        float dv = d[i], sv = s[i];
        float g = 1.f / (1.f + expf(-dv));
        float dg = 0.6f * g;
        d[i] = (1.f - dg) * sv + dg * dv;
    }
}

// H = sigmoid(H)*Hout + (1-sigmoid(H))*H   (in-place)
__global__ void gate_kernel(float* __restrict__ h, const float* __restrict__ hout, int n)
{
    int i = blockIdx.x * blockDim.x + threadIdx.x;
    int stride = gridDim.x * blockDim.x;
    for (; i < n; i += stride) {
        float hv = h[i];
        float g = 1.f / (1.f + expf(-hv));
        h[i] = g * hout[i] + (1.f - g) * hv;
    }
}

// Row L2-normalize: out = z / max(||z||, 1e-12). One warp per row.
__global__ void normalize_kernel(const float* __restrict__ z, float* __restrict__ out,
                                 int rows, int cols)
{
    int gw = (blockIdx.x * blockDim.x + threadIdx.x) >> 5;
    int lane = threadIdx.x & 31;
    int nw = (gridDim.x * blockDim.x) >> 5;
    for (int r = gw; r < rows; r += nw) {
        const float* zr = z + (long long)r * cols;
        float ss = 0.f;
        for (int c = lane; c < cols; c += 32) { float v = zr[c]; ss += v * v; }
#pragma unroll
        for (int o = 16; o > 0; o >>= 1) ss += __shfl_xor_sync(0xffffffffu, ss, o);
        float inv = 1.f / fmaxf(sqrtf(ss), 1e-12f);
        float* orow = out + (long long)r * cols;
        for (int c = lane; c < cols; c += 32) orow[c] = zr[c] * inv;
    }
}

// =============================================================================
// Scope contrastive loss per (b,s). block=(512), grid=(S,B).
// =============================================================================
__global__ void loss_kernel(const float* __restrict__ C11, const float* __restrict__ C12,
                            const float* __restrict__ C21, const float* __restrict__ C22,
                            const int* __restrict__ s_mask, const int* __restrict__ a_mask,
                            float* __restrict__ rowloss)
{
    int s = blockIdx.x, b = blockIdx.y;
    int t = threadIdx.x;
    int lane = t & 31, wid = t >> 5;
    __shared__ float red8[8][16];
    __shared__ float Ssh[8];

    const float it = 1.f / 0.07f;
    long long base = (((long long)b * S_ + s) << 9);
    long long diag = base + s;

    float a   = (float)a_mask[b * S_ + s];
    float sms = (float)s_mask[b * S_ + s];
    float smt = (float)s_mask[b * S_ + t];

    float d11 = C11[diag], d12 = C12[diag], d21 = C21[diag], d22 = C22[diag];
    float dw1 = a * sms * d12;
    float dw2 = a * sms * d21;

    float c11 = C11[base + t], c12 = C12[base + t];
    float c21 = C21[base + t], c22 = C22[base + t];

    float vals[8];
    vals[0] = expf(a * c11 * it);
    vals[1] = expf(a * c12 * it);
    vals[2] = expf(a * smt * c11 * it);
    vals[3] = expf(a * smt * c12 * dw1 * it);
    vals[4] = expf(a * c22 * it);
    vals[5] = expf(a * c21 * it);
    vals[6] = expf(a * smt * c22 * it);
    vals[7] = expf(a * smt * c21 * dw2 * it);

#pragma unroll
    for (int k = 0; k < 8; k++) {
        float v = vals[k];
#pragma unroll
        for (int o = 16; o > 0; o >>= 1) v += __shfl_xor_sync(0xffffffffu, v, o);
        if (lane == 0) red8[k][wid] = v;
    }
    __syncthreads();
    if (t < 8) {
        float x = 0.f;
        for (int w2 = 0; w2 < 16; w2++) x += red8[t][w2];
        Ssh[t] = x;
    }
    __syncthreads();

    if (t == 0) {
        float pos1 = expf(a * sms * d12 * it)
                   + (Ssh[2] - expf(a * sms * d11 * it))
                   + (Ssh[3] - expf(dw1 * dw1 * it));
        float alle1 = Ssh[0] + Ssh[1] - expf(a * d11 * it);
        float l1v = -logf(pos1 / alle1);

        float pos2 = expf(a * sms * d21 * it)
                   + (Ssh[6] - expf(a * sms * d22 * it))
                   + (Ssh[7] - expf(dw2 * dw2 * it));
        float alle2 = Ssh[4] + Ssh[5] - expf(a * d22 * it);
        float l2v = -logf(pos2 / alle2);

        rowloss[b * S_ + s] = 0.5f * (l1v + l2v);
    }
}

__global__ void final_reduce_kernel(const float* __restrict__ rl, float* __restrict__ out)
{
    __shared__ float red[32];
    int tid = threadIdx.x;
    float s = 0.f;
    for (int i = tid; i < BS_; i += 1024) s += rl[i];
#pragma unroll
    for (int o = 16; o > 0; o >>= 1) s += __shfl_xor_sync(0xffffffffu, s, o);
    if ((tid & 31) == 0) red[tid >> 5] = s;
    __syncthreads();
    if (tid < 32) {
        float x = red[tid];
#pragma unroll
        for (int o = 16; o > 0; o >>= 1) x += __shfl_xor_sync(0xffffffffu, x, o);
        if (tid == 0) out[0] = x / (float)BS_;
    }
}

// =============================================================================
extern "C" void kernel_launch(void* const* d_in, const int* in_sizes, int n_in,
                              void* d_out, int out_size)
{
    const float* X     = (const float*)d_in[0];
    const float* adjm  = (const float*)d_in[1];
    const int*   amask = (const int*)d_in[2];
    const int*   smsk  = (const int*)d_in[3];
    const int*   amsk  = (const int*)d_in[4];
    const float* Wq    = (const float*)d_in[5];
    const float* bq    = (const float*)d_in[6];
    const float* Wk    = (const float*)d_in[7];
    const float* bk    = (const float*)d_in[8];
    const float* semW0 = (const float*)d_in[9];
    const float* semb0 = (const float*)d_in[10];
    const float* semW1 = (const float*)d_in[11];
    const float* semb1 = (const float*)d_in[12];
    const float* depW0 = (const float*)d_in[13];
    const float* depb0 = (const float*)d_in[14];
    const float* depW1 = (const float*)d_in[15];
    const float* depb1 = (const float*)d_in[16];
    const float* fc1W  = (const float*)d_in[17];
    const float* fc1b  = (const float*)d_in[18];
    const float* fc2W  = (const float*)d_in[19];
    const float* fc2b  = (const float*)d_in[20];
    const float* fc3W  = (const float*)d_in[21];
    const float* fc3b  = (const float*)d_in[22];
    const float* fc4W  = (const float*)d_in[23];
    const float* fc4b  = (const float*)d_in[24];
    float* out = (float*)d_out;

    float *pQ, *pK, *pS, *pAdj, *pAH1, *pAH2, *pIsem, *pIdep, *pHout, *pHl, *pT,
          *ph1, *ph2, *pn1, *pn2, *pRL;
    cudaGetSymbolAddress((void**)&pQ, g_Q);
    cudaGetSymbolAddress((void**)&pK, g_K);
    cudaGetSymbolAddress((void**)&pS, g_scores);
    cudaGetSymbolAddress((void**)&pAdj, g_adj);
    cudaGetSymbolAddress((void**)&pAH1, g_AH1);
    cudaGetSymbolAddress((void**)&pAH2, g_AH2);
    cudaGetSymbolAddress((void**)&pIsem, g_Isem);
    cudaGetSymbolAddress((void**)&pIdep, g_Idep);
    cudaGetSymbolAddress((void**)&pHout, g_Hout);
    cudaGetSymbolAddress((void**)&pHl, g_Hl);
    cudaGetSymbolAddress((void**)&pT, g_T);
    cudaGetSymbolAddress((void**)&ph1, g_h1);
    cudaGetSymbolAddress((void**)&ph2, g_h2);
    cudaGetSymbolAddress((void**)&pn1, g_n1);
    cudaGetSymbolAddress((void**)&pn2, g_n2);
    cudaGetSymbolAddress((void**)&pRL, g_rowloss);

    float* C11 = pS;
    float* C12 = pS + (long long)B_ * S_ * S_;
    float* C21 = pS + 2LL * B_ * S_ * S_;
    float* C22 = pS + 3LL * B_ * S_ * S_;

    dim3 blk(256);
    const long long SS = (long long)S_ * S_;
    const long long SD = (long long)S_ * D_;
    const long long SM = (long long)S_ * M_;

    // ---- Q/K projections ----
    gemm_tf32_kernel<false><<<dim3(6, 128, 1), blk>>>(X, Wq, bq, pQ, BS_, D_, D_, D_, D_, D_,
                                                      1, 0, 0, 0, 0, 0, 1.f, 0);
    gemm_tf32_kernel<false><<<dim3(6, 128, 1), blk>>>(X, Wk, bk, pK, BS_, D_, D_, D_, D_, D_,
                                                      1, 0, 0, 0, 0, 0, 1.f, 0);

    // ---- per-head scores = Q_bh @ K_bh^T / sqrt(dk) ----
    float alpha = 1.0f / sqrtf((float)DK_);
    gemm_tf32_kernel<true><<<dim3(4, 4, B_ * H_), blk>>>(pQ, pK, nullptr, pS,
                                                         S_, S_, DK_, D_, D_, S_,
                                                         H_, SD, DK_, SD, DK_, SS, alpha, 0);

    // ---- masked softmax + head mean + diag/row-mask -> adj_ag ----
    softmax_mean_kernel<<<dim3(S_, B_), 256>>>(pS, amask, pAdj);

    // ---- Layer 0 ----
    gemm_tf32_kernel<false><<<dim3(6, 4, B_), blk>>>(pAdj, X, nullptr, pAH1, S_, D_, S_, S_, D_, D_,
                                                     1, SS, 0, SD, 0, SD, 1.f, 0);
    gemm_tf32_kernel<false><<<dim3(3, 128, 1), blk>>>(pAH1, semW0, semb0, pIsem, BS_, M_, D_, D_, M_, M_,
                                                      1, 0, 0, 0, 0, 0, 1.f, 0);
    gemm_tf32_kernel<false><<<dim3(6, 4, B_), blk>>>(adjm, X, nullptr, pAH2, S_, D_, S_, S_, D_, D_,
                                                     1, SS, 0, SD, 0, SD, 1.f, 0);
    gemm_tf32_kernel<false><<<dim3(3, 128, 1), blk>>>(pAH2, depW0, depb0, pIdep, BS_, M_, D_, D_, M_, M_,
                                                      1, 0, 0, 0, 0, 0, 1.f, 0);
    combine_kernel<<<4096, 256>>>(pIsem, pIdep, NM_);
    gemm_tf32_kernel<false><<<dim3(3, 128, 1), blk>>>(pIdep, fc3W, fc3b, pHout, BS_, M_, M_, M_, M_, M_,
                                                      1, 0, 0, 0, 0, 0, 1.f, 1);
    gemm_tf32_kernel<false><<<dim3(3, 128, 1), blk>>>(X, fc4W, fc4b, pHl, BS_, M_, D_, D_, M_, M_,
                                                      1, 0, 0, 0, 0, 0, 1.f, 0);
    gate_kernel<<<4096, 256>>>(pHl, pHout, NM_);

    // ---- Layer 1 ----
    gemm_tf32_kernel<false><<<dim3(3, 4, B_), blk>>>(pAdj, pHl, nullptr, pAH1, S_, M_, S_, S_, M_, M_,
                                                     1, SS, 0, SM, 0, SM, 1.f, 0);
    gemm_tf32_kernel<false><<<dim3(3, 128, 1), blk>>>(pAH1, semW1, semb1, pIsem, BS_, M_, M_, M_, M_, M_,
                                                      1, 0, 0, 0, 0, 0, 1.f, 0);
    gemm_tf32_kernel<false><<<dim3(3, 4, B_), blk>>>(adjm, pHl, nullptr, pAH2, S_, M_, S_, S_, M_, M_,
                                                     1, SS, 0, SM, 0, SM, 1.f, 0);
    gemm_tf32_kernel<false><<<dim3(3, 128, 1), blk>>>(pAH2, depW1, depb1, pIdep, BS_, M_, M_, M_, M_, M_,
                                                      1, 0, 0, 0, 0, 0, 1.f, 0);
    combine_kernel<<<4096, 256>>>(pIsem, pIdep, NM_);
    gemm_tf32_kernel<false><<<dim3(3, 128, 1), blk>>>(pIdep, fc3W, fc3b, pHout, BS_, M_, M_, M_, M_, M_,
                                                      1, 0, 0, 0, 0, 0, 1.f, 1);
    gate_kernel<<<4096, 256>>>(pHl, pHout, NM_);   // final H_l

    // ---- projection head ----
    gemm_tf32_kernel<false><<<dim3(1, 128, 1), blk>>>(pHl, fc1W, fc1b, pT, BS_, 32, M_, M_, 32, 32,
                                                      1, 0, 0, 0, 0, 0, 1.f, 2);
    gemm_tf32_kernel<false><<<dim3(3, 128, 1), blk>>>(pT, fc2W, fc2b, ph1, BS_, M_, 32, 32, M_, M_,
                                                      1, 0, 0, 0, 0, 0, 1.f, 0);
    gemm_tf32_kernel<false><<<dim3(1, 128, 1), blk>>>(pIsem, fc1W, fc1b, pT, BS_, 32, M_, M_, 32, 32,
                                                      1, 0, 0, 0, 0, 0, 1.f, 2);
    gemm_tf32_kernel<false><<<dim3(3, 128, 1), blk>>>(pT, fc2W, fc2b, ph2, BS_, M_, 32, 32, M_, M_,
                                                      1, 0, 0, 0, 0, 0, 1.f, 0);

    // ---- normalize rows ----
    normalize_kernel<<<2048, 256>>>(ph1, pn1, BS_, M_);
    normalize_kernel<<<2048, 256>>>(ph2, pn2, BS_, M_);

    // ---- cosine similarity matrices (batched NT, K=384) ----
    gemm_tf32_kernel<true><<<dim3(4, 4, B_), blk>>>(pn1, pn1, nullptr, C11, S_, S_, M_, M_, M_, S_,
                                                    1, SM, 0, SM, 0, SS, 1.f, 0);
    gemm_tf32_kernel<true><<<dim3(4, 4, B_), blk>>>(pn1, pn2, nullptr, C12, S_, S_, M_, M_, M_, S_,
                                                    1, SM, 0, SM, 0, SS, 1.f, 0);
    gemm_tf32_kernel<true><<<dim3(4, 4, B_), blk>>>(pn2, pn1, nullptr, C21, S_, S_, M_, M_, M_, S_,
                                                    1, SM, 0, SM, 0, SS, 1.f, 0);
    gemm_tf32_kernel<true><<<dim3(4, 4, B_), blk>>>(pn2, pn2, nullptr, C22, S_, S_, M_, M_, M_, S_,
                                                    1, SM, 0, SM, 0, SS, 1.f, 0);

    // ---- loss ----
    loss_kernel<<<dim3(S_, B_), 512>>>(C11, C12, C21, C22, smsk, amsk, pRL);
    final_reduce_kernel<<<1, 1024>>>(pRL, out);
}

// round 4
// speedup vs baseline: 3.3247x; 1.0732x over previous
#include <cuda_runtime.h>
#include <math.h>
#include <stdint.h>

// Problem dims (fixed by reference setup_inputs)
#define B_   32
#define S_   512
#define D_   768
#define M_   384
#define H_   8
#define DK_  96
#define BS_  (B_*S_)          // 16384 rows total
#define NM_  (BS_*M_)         // 6291456 elems of [BS,384]

#define STAGES   4
#define A_STAGE  (128*20)     // floats per A stage ([128 rows][16+4 pad])
#define B_STAGE  (128*20)     // floats per B stage (NT: [128][20]; NN uses [16][136] <= this)
#define SMEM_BYTES ((STAGES*(A_STAGE+B_STAGE))*4)   // 81920 B

// ---------------- static device scratch (no runtime alloc allowed) -------------
__device__ float g_Q    [BS_*D_];
__device__ float g_K    [BS_*D_];
__device__ float g_scores[67108864];      // [B,H,S,S]; later aliased for C11,C12,C21,C22
__device__ float g_adj  [B_*S_*S_];
__device__ float g_AH1  [BS_*D_];
__device__ float g_AH2  [BS_*D_];
__device__ float g_Isem [NM_];
__device__ float g_Idep [NM_];
__device__ float g_Hl   [NM_];
__device__ float g_T    [BS_*32];
__device__ float g_h1   [NM_];
__device__ float g_h2   [NM_];
__device__ float g_n1   [NM_];
__device__ float g_n2   [NM_];
__device__ float g_rowloss[BS_];

__device__ __forceinline__ void cp16(uint32_t dst, const float* src) {
    asm volatile("cp.async.ca.shared.global [%0], [%1], 16;\n" :: "r"(dst), "l"(src));
}

// =============================================================================
// TF32 tensor-core GEMM (mma.sync.m16n8k8), fp32 accumulate, cp.async 4-stage.
//   C[z] = epi(alpha * A[z] @ op(B[z]) + bias)
// TRANSB=false: B is [K][N] row-major.  TRANSB=true: B is [N][K] row-major (NT).
// Tile 128x128x16, 256 threads (8 warps, 2x4 warp layout, 64x32 warp tiles).
// Requirements: M%128==0, K%16==0; NT requires N%128==0; NN: N%4==0 (zero-fill).
// Inputs consumed as raw fp32 bits -> HW tf32 truncation (RZ); fp32 accumulate.
// act: 0 none, 1 relu, 2 elu, 3 relu+gate(aux, in-place), 4 sigmoid-combine(aux)
// =============================================================================
template<bool TRANSB>
__global__ __launch_bounds__(256)
void gemm_tf32_kernel(const float* __restrict__ Abase, const float* __restrict__ Bbase,
                      const float* __restrict__ bias, float* __restrict__ Cbase,
                      const float* __restrict__ Eaux,
                      int M, int N, int K, int lda, int ldb, int ldc,
                      int nInner, long long sAo, long long sAi,
                      long long sBo, long long sBi, long long sC,
                      float alpha, int act)
{
    extern __shared__ float smem[];
    float* Asm = smem;
    float* Bsm = smem + STAGES * A_STAGE;

    int z  = blockIdx.z;
    int zo = z / nInner, zi = z - zo * nInner;
    const float* A  = Abase + (long long)zo * sAo + (long long)zi * sAi;
    const float* Bm = Bbase + (long long)zo * sBo + (long long)zi * sBi;
    float*       C  = Cbase + (long long)z * sC;
    int bm = blockIdx.y * 128;
    int bn = blockIdx.x * 128;

    int tid  = threadIdx.x;
    int lane = tid & 31;
    int wid  = tid >> 5;
    int wm   = wid >> 2;      // 0..1  (M dir, 64 rows)
    int wn   = wid & 3;       // 0..3  (N dir, 32 cols)

    uint32_t smem_u32 = (uint32_t)__cvta_generic_to_shared(smem);
    uint32_t a_u32 = smem_u32;
    uint32_t b_u32 = smem_u32 + STAGES * A_STAGE * 4;

    float acc[4][4][4];
#pragma unroll
    for (int i = 0; i < 4; i++)
#pragma unroll
        for (int j = 0; j < 4; j++)
#pragma unroll
            for (int r = 0; r < 4; r++) acc[i][j][r] = 0.f;

    int KT = K >> 4;

    // ---- async tile load ----
    auto issue_load = [&](int stage, int kt) {
        int k0 = kt << 4;
        // A: 512 chunks of 16B, 2 per thread
#pragma unroll
        for (int c = 0; c < 2; c++) {
            int ci  = tid + (c << 8);
            int row = ci >> 2, kc = (ci & 3) << 2;
            uint32_t dst = a_u32 + (uint32_t)((stage * A_STAGE + row * 20 + kc) * 4);
            cp16(dst, A + (long long)(bm + row) * lda + k0 + kc);
        }
        if (TRANSB) {
#pragma unroll
            for (int c = 0; c < 2; c++) {
                int ci  = tid + (c << 8);
                int row = ci >> 2, kc = (ci & 3) << 2;
                uint32_t dst = b_u32 + (uint32_t)((stage * B_STAGE + row * 20 + kc) * 4);
                cp16(dst, Bm + (long long)(bn + row) * ldb + k0 + kc);
            }
        } else {
#pragma unroll
            for (int c = 0; c < 2; c++) {
                int ci  = tid + (c << 8);
                int row = ci >> 5, nc = (ci & 31) << 2;
                int gc  = bn + nc;
                uint32_t dst = b_u32 + (uint32_t)((stage * B_STAGE + row * 136 + nc) * 4);
                if (gc < N) {
                    cp16(dst, Bm + (long long)(k0 + row) * ldb + gc);
                } else {
                    float4 zz = make_float4(0.f, 0.f, 0.f, 0.f);
                    asm volatile("st.shared.v4.f32 [%0], {%1,%2,%3,%4};\n"
                                 :: "r"(dst), "f"(zz.x), "f"(zz.y), "f"(zz.z), "f"(zz.w));
                }
            }
        }
    };

    // ---- compute one smem stage ----
    auto compute = [&](int buf) {
        uint32_t a_base = a_u32 + (uint32_t)(buf * A_STAGE * 4);
        const float* Bst = Bsm + buf * B_STAGE;
#pragma unroll
        for (int ks = 0; ks < 16; ks += 8) {
            uint32_t a[4][4];
#pragma unroll
            for (int mi = 0; mi < 4; mi++) {
                int row = wm * 64 + mi * 16 + (lane & 15);
                uint32_t addr = a_base + (uint32_t)((row * 20 + ks + ((lane >> 4) << 2)) * 4);
                asm volatile("ldmatrix.sync.aligned.m8n8.x4.shared.b16 {%0,%1,%2,%3}, [%4];"
                             : "=r"(a[mi][0]), "=r"(a[mi][1]), "=r"(a[mi][2]), "=r"(a[mi][3])
                             : "r"(addr));
            }
            uint32_t bf[4][2];
#pragma unroll
            for (int ni = 0; ni < 4; ni++) {
                int coln = wn * 32 + ni * 8 + (lane >> 2);
                if (TRANSB) {
                    bf[ni][0] = __float_as_uint(Bst[coln * 20 + ks + (lane & 3)]);
                    bf[ni][1] = __float_as_uint(Bst[coln * 20 + ks + (lane & 3) + 4]);
                } else {
                    bf[ni][0] = __float_as_uint(Bst[(ks + (lane & 3))     * 136 + coln]);
                    bf[ni][1] = __float_as_uint(Bst[(ks + (lane & 3) + 4) * 136 + coln]);
                }
            }
#pragma unroll
            for (int mi = 0; mi < 4; mi++)
#pragma unroll
                for (int ni = 0; ni < 4; ni++) {
                    asm volatile(
                        "mma.sync.aligned.m16n8k8.row.col.f32.tf32.tf32.f32 "
                        "{%0,%1,%2,%3}, {%4,%5,%6,%7}, {%8,%9}, {%0,%1,%2,%3};"
                        : "+f"(acc[mi][ni][0]), "+f"(acc[mi][ni][1]),
                          "+f"(acc[mi][ni][2]), "+f"(acc[mi][ni][3])
                        : "r"(a[mi][0]), "r"(a[mi][1]), "r"(a[mi][2]), "r"(a[mi][3]),
                          "r"(bf[ni][0]), "r"(bf[ni][1]));
                }
        }
    };

    // ---- prologue: preload STAGES-1 stages (commit every stage to keep count) ----
#pragma unroll
    for (int s = 0; s < STAGES - 1; s++) {
        if (s < KT) issue_load(s, s);
        asm volatile("cp.async.commit_group;\n");
    }

    // ---- mainloop ----
    for (int kt = 0; kt < KT; kt++) {
        asm volatile("cp.async.wait_group %0;\n" :: "n"(STAGES - 2));
        __syncthreads();
        int nk = kt + STAGES - 1;
        if (nk < KT) issue_load(nk & (STAGES - 1), nk);
        asm volatile("cp.async.commit_group;\n");
        compute(kt & (STAGES - 1));
    }

    // ---- epilogue ----
    int g = lane >> 2, q = lane & 3;
#pragma unroll
    for (int mi = 0; mi < 4; mi++) {
#pragma unroll
        for (int ni = 0; ni < 4; ni++) {
            int col = bn + wn * 32 + ni * 8 + 2 * q;
            if (col >= N) continue;
            float bb0 = bias ? bias[col]     : 0.f;
            float bb1 = bias ? bias[col + 1] : 0.f;
#pragma unroll
            for (int half = 0; half < 2; half++) {
                int r = bm + wm * 64 + mi * 16 + g + half * 8;
                long long off = (long long)r * ldc + col;
                float v0 = acc[mi][ni][half * 2 + 0] * alpha + bb0;
                float v1 = acc[mi][ni][half * 2 + 1] * alpha + bb1;
                if (act == 1) { v0 = fmaxf(v0, 0.f); v1 = fmaxf(v1, 0.f); }
                else if (act == 2) {
                    v0 = v0 > 0.f ? v0 : (expf(v0) - 1.f);
                    v1 = v1 > 0.f ? v1 : (expf(v1) - 1.f);
                } else if (act == 3) {        // relu then gate with aux (in-place target)
                    v0 = fmaxf(v0, 0.f); v1 = fmaxf(v1, 0.f);
                    float2 hl = *reinterpret_cast<const float2*>(Eaux + off);
                    float g0 = 1.f / (1.f + expf(-hl.x));
                    float g1 = 1.f / (1.f + expf(-hl.y));
                    v0 = g0 * v0 + (1.f - g0) * hl.x;
                    v1 = g1 * v1 + (1.f - g1) * hl.y;
                } else if (act == 4) {        // gated combine with aux = I_sem
                    float2 e = *reinterpret_cast<const float2*>(Eaux + off);
                    float g0 = 0.6f / (1.f + expf(-v0));
                    float g1 = 0.6f / (1.f + expf(-v1));
                    v0 = (1.f - g0) * e.x + g0 * v0;
                    v1 = (1.f - g1) * e.y + g1 * v1;
                }
                float2 o; o.x = v0; o.y = v1;
                *reinterpret_cast<float2*>(&C[off]) = o;
            }
        }
    }
}

// =============================================================================
// Masked softmax over keys + mean over 8 heads + diag->1 + row mask.
// One warp per head. grid=(S,B), block=256.
// =============================================================================
__global__ void softmax_mean_kernel(const float* __restrict__ scores,
                                    const int* __restrict__ attn_mask,
                                    float* __restrict__ adj)
{
    int s = blockIdx.x, b = blockIdx.y;
    int tid = threadIdx.x;
    int lane = tid & 31, h = tid >> 5;
    __shared__ float accs[512];

    accs[tid] = 0.f; accs[tid + 256] = 0.f;
    __syncthreads();

    const float* row = scores + ((((long long)b * H_ + h) * S_ + s) << 9);
    const int* cm = attn_mask + b * S_;

    float v[16];
    float mx = -INFINITY;
#pragma unroll
    for (int j = 0; j < 16; j++) {
        int c = lane + (j << 5);
        float x = row[c];
        if (cm[c] == 0) x = -10000.f;
        v[j] = x;
        mx = fmaxf(mx, x);
    }
#pragma unroll
    for (int o = 16; o > 0; o >>= 1) mx = fmaxf(mx, __shfl_xor_sync(0xffffffffu, mx, o));

    float sum = 0.f;
#pragma unroll
    for (int j = 0; j < 16; j++) { v[j] = expf(v[j] - mx); sum += v[j]; }
#pragma unroll
    for (int o = 16; o > 0; o >>= 1) sum += __shfl_xor_sync(0xffffffffu, sum, o);
    float inv = 1.f / sum;

#pragma unroll
    for (int j = 0; j < 16; j++) atomicAdd(&accs[lane + (j << 5)], v[j] * inv);
    __syncthreads();

    float rmask = (float)attn_mask[b * S_ + s];
    long long obase = (((long long)b * S_ + s) << 9);
#pragma unroll
    for (int k = 0; k < 2; k++) {
        int c = tid + (k << 8);
        float val = (c == s) ? 1.f : accs[c] * 0.125f;
        adj[obase + c] = val * rmask;
    }
}

// Per-batch 512x512 transpose: out[b][s][t] = in[b][t][s]
__global__ void transpose_kernel(const float* __restrict__ in, float* __restrict__ out)
{
    __shared__ float tile[32][33];
    int b = blockIdx.z;
    int s0 = blockIdx.x << 5, t0 = blockIdx.y << 5;
    const float* ib = in  + (long long)b * S_ * S_;
    float*       ob = out + (long long)b * S_ * S_;
    int tx = threadIdx.x, ty = threadIdx.y;
#pragma unroll
    for (int j = ty; j < 32; j += 8)
        tile[j][tx] = ib[(long long)(t0 + j) * S_ + s0 + tx];
    __syncthreads();
#pragma unroll
    for (int j = ty; j < 32; j += 8)
        ob[(long long)(s0 + j) * S_ + t0 + tx] = tile[tx][j];
}

// Row L2-normalize: out = z / max(||z||, 1e-12). One warp per row.
__global__ void normalize_kernel(const float* __restrict__ z, float* __restrict__ out,
                                 int rows, int cols)
{
    int gw = (blockIdx.x * blockDim.x + threadIdx.x) >> 5;
    int lane = threadIdx.x & 31;
    int nw = (gridDim.x * blockDim.x) >> 5;
    for (int r = gw; r < rows; r += nw) {
        const float* zr = z + (long long)r * cols;
        float ss = 0.f;
        for (int c = lane; c < cols; c += 32) { float v = zr[c]; ss += v * v; }
#pragma unroll
        for (int o = 16; o > 0; o >>= 1) ss += __shfl_xor_sync(0xffffffffu, ss, o);
        float inv = 1.f / fmaxf(sqrtf(ss), 1e-12f);
        float* orow = out + (long long)r * cols;
        for (int c = lane; c < cols; c += 32) orow[c] = zr[c] * inv;
    }
}

// =============================================================================
// Scope contrastive loss per (b,s). block=(512), grid=(S,B).
// =============================================================================
__global__ void loss_kernel(const float* __restrict__ C11, const float* __restrict__ C12,
                            const float* __restrict__ C21, const float* __restrict__ C22,
                            const int* __restrict__ s_mask, const int* __restrict__ a_mask,
                            float* __restrict__ rowloss)
{
    int s = blockIdx.x, b = blockIdx.y;
    int t = threadIdx.x;
    int lane = t & 31, wid = t >> 5;
    __shared__ float red8[8][16];
    __shared__ float Ssh[8];

    const float it = 1.f / 0.07f;
    long long base = (((long long)b * S_ + s) << 9);
    long long diag = base + s;

    float a   = (float)a_mask[b * S_ + s];
    float sms = (float)s_mask[b * S_ + s];
    float smt = (float)s_mask[b * S_ + t];

    float d11 = C11[diag], d12 = C12[diag], d21 = C21[diag], d22 = C22[diag];
    float dw1 = a * sms * d12;
    float dw2 = a * sms * d21;

    float c11 = C11[base + t], c12 = C12[base + t];
    float c21 = C21[base + t], c22 = C22[base + t];

    float vals[8];
    vals[0] = expf(a * c11 * it);
    vals[1] = expf(a * c12 * it);
    vals[2] = expf(a * smt * c11 * it);
    vals[3] = expf(a * smt * c12 * dw1 * it);
    vals[4] = expf(a * c22 * it);
    vals[5] = expf(a * c21 * it);
    vals[6] = expf(a * smt * c22 * it);
    vals[7] = expf(a * smt * c21 * dw2 * it);

#pragma unroll
    for (int k = 0; k < 8; k++) {
        float v = vals[k];
#pragma unroll
        for (int o = 16; o > 0; o >>= 1) v += __shfl_xor_sync(0xffffffffu, v, o);
        if (lane == 0) red8[k][wid] = v;
    }
    __syncthreads();
    if (t < 8) {
        float x = 0.f;
        for (int w2 = 0; w2 < 16; w2++) x += red8[t][w2];
        Ssh[t] = x;
    }
    __syncthreads();

    if (t == 0) {
        float pos1 = expf(a * sms * d12 * it)
                   + (Ssh[2] - expf(a * sms * d11 * it))
                   + (Ssh[3] - expf(dw1 * dw1 * it));
        float alle1 = Ssh[0] + Ssh[1] - expf(a * d11 * it);
        float l1v = -logf(pos1 / alle1);

        float pos2 = expf(a * sms * d21 * it)
                   + (Ssh[6] - expf(a * sms * d22 * it))
                   + (Ssh[7] - expf(dw2 * dw2 * it));
        float alle2 = Ssh[4] + Ssh[5] - expf(a * d22 * it);
        float l2v = -logf(pos2 / alle2);

        rowloss[b * S_ + s] = 0.5f * (l1v + l2v);
    }
}

__global__ void final_reduce_kernel(const float* __restrict__ rl, float* __restrict__ out)
{
    __shared__ float red[32];
    int tid = threadIdx.x;
    float s = 0.f;
    for (int i = tid; i < BS_; i += 1024) s += rl[i];
#pragma unroll
    for (int o = 16; o > 0; o >>= 1) s += __shfl_xor_sync(0xffffffffu, s, o);
    if ((tid & 31) == 0) red[tid >> 5] = s;
    __syncthreads();
    if (tid < 32) {
        float x = red[tid];
#pragma unroll
        for (int o = 16; o > 0; o >>= 1) x += __shfl_xor_sync(0xffffffffu, x, o);
        if (tid == 0) out[0] = x / (float)BS_;
    }
}

// =============================================================================
extern "C" void kernel_launch(void* const* d_in, const int* in_sizes, int n_in,
                              void* d_out, int out_size)
{
    const float* X     = (const float*)d_in[0];
    const float* adjm  = (const float*)d_in[1];
    const int*   amask = (const int*)d_in[2];
    const int*   smsk  = (const int*)d_in[3];
    const int*   amsk  = (const int*)d_in[4];
    const float* Wq    = (const float*)d_in[5];
    const float* bq    = (const float*)d_in[6];
    const float* Wk    = (const float*)d_in[7];
    const float* bk    = (const float*)d_in[8];
    const float* semW0 = (const float*)d_in[9];
    const float* semb0 = (const float*)d_in[10];
    const float* semW1 = (const float*)d_in[11];
    const float* semb1 = (const float*)d_in[12];
    const float* depW0 = (const float*)d_in[13];
    const float* depb0 = (const float*)d_in[14];
    const float* depW1 = (const float*)d_in[15];
    const float* depb1 = (const float*)d_in[16];
    const float* fc1W  = (const float*)d_in[17];
    const float* fc1b  = (const float*)d_in[18];
    const float* fc2W  = (const float*)d_in[19];
    const float* fc2b  = (const float*)d_in[20];
    const float* fc3W  = (const float*)d_in[21];
    const float* fc3b  = (const float*)d_in[22];
    const float* fc4W  = (const float*)d_in[23];
    const float* fc4b  = (const float*)d_in[24];
    float* out = (float*)d_out;

    static bool attr_done = false;
    if (!attr_done) {
        cudaFuncSetAttribute(gemm_tf32_kernel<false>,
                             cudaFuncAttributeMaxDynamicSharedMemorySize, SMEM_BYTES);
        cudaFuncSetAttribute(gemm_tf32_kernel<true>,
                             cudaFuncAttributeMaxDynamicSharedMemorySize, SMEM_BYTES);
        attr_done = true;
    }

    float *pQ, *pK, *pS, *pAdj, *pAH1, *pAH2, *pIsem, *pIdep, *pHl, *pT,
          *ph1, *ph2, *pn1, *pn2, *pRL;
    cudaGetSymbolAddress((void**)&pQ, g_Q);
    cudaGetSymbolAddress((void**)&pK, g_K);
    cudaGetSymbolAddress((void**)&pS, g_scores);
    cudaGetSymbolAddress((void**)&pAdj, g_adj);
    cudaGetSymbolAddress((void**)&pAH1, g_AH1);
    cudaGetSymbolAddress((void**)&pAH2, g_AH2);
    cudaGetSymbolAddress((void**)&pIsem, g_Isem);
    cudaGetSymbolAddress((void**)&pIdep, g_Idep);
    cudaGetSymbolAddress((void**)&pHl, g_Hl);
    cudaGetSymbolAddress((void**)&pT, g_T);
    cudaGetSymbolAddress((void**)&ph1, g_h1);
    cudaGetSymbolAddress((void**)&ph2, g_h2);
    cudaGetSymbolAddress((void**)&pn1, g_n1);
    cudaGetSymbolAddress((void**)&pn2, g_n2);
    cudaGetSymbolAddress((void**)&pRL, g_rowloss);

    float* C11 = pS;
    float* C12 = pS + (long long)B_ * S_ * S_;
    float* C21 = pS + 2LL * B_ * S_ * S_;
    float* C22 = pS + 3LL * B_ * S_ * S_;

    dim3 blk(256);
    const long long SS = (long long)S_ * S_;
    const long long SD = (long long)S_ * D_;
    const long long SM = (long long)S_ * M_;
    const int SB = SMEM_BYTES;

    // ---- Q/K projections ----
    gemm_tf32_kernel<false><<<dim3(6, 128, 1), blk, SB>>>(X, Wq, bq, pQ, nullptr,
        BS_, D_, D_, D_, D_, D_, 1, 0, 0, 0, 0, 0, 1.f, 0);
    gemm_tf32_kernel<false><<<dim3(6, 128, 1), blk, SB>>>(X, Wk, bk, pK, nullptr,
        BS_, D_, D_, D_, D_, D_, 1, 0, 0, 0, 0, 0, 1.f, 0);

    // ---- per-head scores = Q_bh @ K_bh^T / sqrt(dk) ----
    float alpha = 1.0f / sqrtf((float)DK_);
    gemm_tf32_kernel<true><<<dim3(4, 4, B_ * H_), blk, SB>>>(pQ, pK, nullptr, pS, nullptr,
        S_, S_, DK_, D_, D_, S_, H_, SD, DK_, SD, DK_, SS, alpha, 0);

    // ---- masked softmax + head mean + diag/row-mask -> adj_ag ----
    softmax_mean_kernel<<<dim3(S_, B_), 256>>>(pS, amask, pAdj);

    // ---- Layer 0 ----
    gemm_tf32_kernel<false><<<dim3(6, 4, B_), blk, SB>>>(pAdj, X, nullptr, pAH1, nullptr,
        S_, D_, S_, S_, D_, D_, 1, SS, 0, SD, 0, SD, 1.f, 0);
    gemm_tf32_kernel<false><<<dim3(3, 128, 1), blk, SB>>>(pAH1, semW0, semb0, pIsem, nullptr,
        BS_, M_, D_, D_, M_, M_, 1, 0, 0, 0, 0, 0, 1.f, 0);
    gemm_tf32_kernel<false><<<dim3(6, 4, B_), blk, SB>>>(adjm, X, nullptr, pAH2, nullptr,
        S_, D_, S_, S_, D_, D_, 1, SS, 0, SD, 0, SD, 1.f, 0);
    // I_dep GEMM with fused gated-combine (reads I_sem) -> I_com into pIdep
    gemm_tf32_kernel<false><<<dim3(3, 128, 1), blk, SB>>>(pAH2, depW0, depb0, pIdep, pIsem,
        BS_, M_, D_, D_, M_, M_, 1, 0, 0, 0, 0, 0, 1.f, 4);
    // H_l = X @ fc4 + b (must precede gated fc3)
    gemm_tf32_kernel<false><<<dim3(3, 128, 1), blk, SB>>>(X, fc4W, fc4b, pHl, nullptr,
        BS_, M_, D_, D_, M_, M_, 1, 0, 0, 0, 0, 0, 1.f, 0);
    // H_out = relu(I_com @ fc3 + b), fused gate with H_l (in-place)
    gemm_tf32_kernel<false><<<dim3(3, 128, 1), blk, SB>>>(pIdep, fc3W, fc3b, pHl, pHl,
        BS_, M_, M_, M_, M_, M_, 1, 0, 0, 0, 0, 0, 1.f, 3);

    // ---- Layer 1 ----
    gemm_tf32_kernel<false><<<dim3(3, 4, B_), blk, SB>>>(pAdj, pHl, nullptr, pAH1, nullptr,
        S_, M_, S_, S_, M_, M_, 1, SS, 0, SM, 0, SM, 1.f, 0);
    gemm_tf32_kernel<false><<<dim3(3, 128, 1), blk, SB>>>(pAH1, semW1, semb1, pIsem, nullptr,
        BS_, M_, M_, M_, M_, M_, 1, 0, 0, 0, 0, 0, 1.f, 0);
    gemm_tf32_kernel<false><<<dim3(3, 4, B_), blk, SB>>>(adjm, pHl, nullptr, pAH2, nullptr,
        S_, M_, S_, S_, M_, M_, 1, SS, 0, SM, 0, SM, 1.f, 0);
    gemm_tf32_kernel<false><<<dim3(3, 128, 1), blk, SB>>>(pAH2, depW1, depb1, pIdep, pIsem,
        BS_, M_, M_, M_, M_, M_, 1, 0, 0, 0, 0, 0, 1.f, 4);
    gemm_tf32_kernel<false><<<dim3(3, 128, 1), blk, SB>>>(pIdep, fc3W, fc3b, pHl, pHl,
        BS_, M_, M_, M_, M_, M_, 1, 0, 0, 0, 0, 0, 1.f, 3);   // final H_l

    // ---- projection head ----
    gemm_tf32_kernel<false><<<dim3(1, 128, 1), blk, SB>>>(pHl, fc1W, fc1b, pT, nullptr,
        BS_, 32, M_, M_, 32, 32, 1, 0, 0, 0, 0, 0, 1.f, 2);
    gemm_tf32_kernel<false><<<dim3(3, 128, 1), blk, SB>>>(pT, fc2W, fc2b, ph1, nullptr,
        BS_, M_, 32, 32, M_, M_, 1, 0, 0, 0, 0, 0, 1.f, 0);
    gemm_tf32_kernel<false><<<dim3(1, 128, 1), blk, SB>>>(pIsem, fc1W, fc1b, pT, nullptr,
        BS_, 32, M_, M_, 32, 32, 1, 0, 0, 0, 0, 0, 1.f, 2);
    gemm_tf32_kernel<false><<<dim3(3, 128, 1), blk, SB>>>(pT, fc2W, fc2b, ph2, nullptr,
        BS_, M_, 32, 32, M_, M_, 1, 0, 0, 0, 0, 0, 1.f, 0);

    // ---- normalize rows ----
    normalize_kernel<<<2048, 256>>>(ph1, pn1, BS_, M_);
    normalize_kernel<<<2048, 256>>>(ph2, pn2, BS_, M_);

    // ---- cosine similarity matrices: 3 GEMMs + 1 transpose (C21 = C12^T) ----
    gemm_tf32_kernel<true><<<dim3(4, 4, B_), blk, SB>>>(pn1, pn1, nullptr, C11, nullptr,
        S_, S_, M_, M_, M_, S_, 1, SM, 0, SM, 0, SS, 1.f, 0);
    gemm_tf32_kernel<true><<<dim3(4, 4, B_), blk, SB>>>(pn1, pn2, nullptr, C12, nullptr,
        S_, S_, M_, M_, M_, S_, 1, SM, 0, SM, 0, SS, 1.f, 0);
    gemm_tf32_kernel<true><<<dim3(4, 4, B_), blk, SB>>>(pn2, pn2, nullptr, C22, nullptr,
        S_, S_, M_, M_, M_, S_, 1, SM, 0, SM, 0, SS, 1.f, 0);
    transpose_kernel<<<dim3(16, 16, B_), dim3(32, 8)>>>(C12, C21);

    // ---- loss ----
    loss_kernel<<<dim3(S_, B_), 512>>>(C11, C12, C21, C22, smsk, amsk, pRL);
    final_reduce_kernel<<<1, 1024>>>(pRL, out);
}

// round 7
// speedup vs baseline: 4.3783x; 1.3169x over previous
#include <cuda_runtime.h>
#include <cuda_fp16.h>
#include <math.h>
#include <stdint.h>

#define B_   32
#define S_   512
#define D_   768
#define M_   384
#define H_   8
#define DK_  96
#define BS_  (B_*S_)
#define NM_  (BS_*M_)

#define STG    4
#define PITCH  40                 // halves per smem row (32 + 8 pad = 5x16B)
#define AST    (128*PITCH)        // halves per stage (A or B)
#define GSMEM  (STG*2*AST*2)      // bytes = 81920

// ---------------- fp32 scratch ----------------
__device__ float g_scores[67108864];   // [B,H,S,S]; later C11,C12,C21,C22
__device__ float g_Isem [NM_];
__device__ float g_Hl   [NM_];
__device__ float g_h1   [NM_];
__device__ float g_h2   [NM_];
__device__ float g_rowloss[BS_];
// ---------------- fp16 scratch ----------------
__device__ __half g_Xh   [BS_*D_];
__device__ __half g_XTh  [BS_*D_];     // [B][D][S]
__device__ __half g_adjmh[B_*S_*S_];
__device__ __half g_Qh   [BS_*D_];
__device__ __half g_Kh   [BS_*D_];
__device__ __half g_adjh [B_*S_*S_];
__device__ __half g_AH1h [BS_*D_];
__device__ __half g_AH2h [BS_*D_];
__device__ __half g_Isemh[NM_];
__device__ __half g_Icomh[NM_];
__device__ __half g_Hlh  [NM_];
__device__ __half g_HTh  [NM_];        // [B][M][S]
__device__ __half g_Th   [BS_*32];
__device__ __half g_n1h  [NM_];
__device__ __half g_n2h  [NM_];
// fp16 transposed weights
__device__ __half g_WqT [D_*D_];
__device__ __half g_WkT [D_*D_];
__device__ __half g_sW0T[M_*D_];
__device__ __half g_dW0T[M_*D_];
__device__ __half g_fc4T[M_*D_];
__device__ __half g_sW1T[M_*M_];
__device__ __half g_dW1T[M_*M_];
__device__ __half g_fc3T[M_*M_];
__device__ __half g_fc1T[32*M_];
__device__ __half g_fc2T[M_*32];

__device__ __forceinline__ void cp16(uint32_t dst, const void* src) {
    asm volatile("cp.async.ca.shared.global [%0], [%1], 16;\n" :: "r"(dst), "l"(src));
}

// =============================================================================
// FP16 tensor GEMM (mma.sync.m16n8k16.f32.f16.f16.f32), all-NT:
//   C[z][m,n] = epi(alpha * sum_k A[z][m,k]*B[z][n,k] + bias[n])
// Tile 128x128, BK=32 halves, 4-stage cp.async, 256 thr (8 warps 2x4).
// M%128==0, K%32==0, N%8==0 (N<128 allowed: B rows zero-filled, stores guarded).
// act: 0 none, 1 relu, 2 elu, 3 relu+gate(aux fp32, in-place C32), 4 combine(aux)
// =============================================================================
__global__ __launch_bounds__(256)
void gemm_f16(const __half* __restrict__ Ab, const __half* __restrict__ Bb,
              const float* __restrict__ bias, float* __restrict__ C32,
              __half* __restrict__ C16, const float* __restrict__ Eaux,
              int K, int lda, int ldb, int ldc, int N,
              int nInner, long long sAo, long long sAi,
              long long sBo, long long sBi, long long sC,
              float alpha, int act)
{
    extern __shared__ __half smem[];
    uint32_t sbase = (uint32_t)__cvta_generic_to_shared(smem);
    uint32_t aU = sbase;
    uint32_t bU = sbase + STG * AST * 2;
    __half* Bsm = smem + STG * AST;

    int z  = blockIdx.z;
    int zo = z / nInner, zi = z - zo * nInner;
    const __half* A  = Ab + (long long)zo * sAo + (long long)zi * sAi;
    const __half* Bm = Bb + (long long)zo * sBo + (long long)zi * sBi;
    int bm = blockIdx.y << 7;
    int bn = blockIdx.x << 7;
    int Nb = N - bn; if (Nb > 128) Nb = 128;

    int tid  = threadIdx.x;
    int lane = tid & 31;
    int wid  = tid >> 5;
    int wm   = wid >> 2;
    int wn   = wid & 3;

    float acc[4][4][4];
#pragma unroll
    for (int i = 0; i < 4; i++)
#pragma unroll
        for (int j = 0; j < 4; j++)
#pragma unroll
            for (int r = 0; r < 4; r++) acc[i][j][r] = 0.f;

    int KT = K >> 5;

    auto issue_load = [&](int stage, int kt) {
        int k0 = kt << 5;
#pragma unroll
        for (int c = 0; c < 2; c++) {
            int ci = tid + (c << 8);
            int row = ci >> 2, kq = ci & 3;
            uint32_t ad = aU + (uint32_t)((stage * AST + row * PITCH + kq * 8) * 2);
            cp16(ad, A + (long long)(bm + row) * lda + k0 + kq * 8);
            uint32_t bd = bU + (uint32_t)((stage * AST + row * PITCH + kq * 8) * 2);
            if (row < Nb) {
                cp16(bd, Bm + (long long)(bn + row) * ldb + k0 + kq * 8);
            } else {
                asm volatile("st.shared.v4.b32 [%0], {%1,%1,%1,%1};\n"
                             :: "r"(bd), "r"(0) : "memory");
            }
        }
        asm volatile("cp.async.commit_group;\n" ::: "memory");
    };

    auto compute = [&](int buf) {
        uint32_t a_base = aU + (uint32_t)(buf * AST * 2);
        const __half* Bst = Bsm + buf * AST;
#pragma unroll
        for (int ks = 0; ks < 32; ks += 16) {
            uint32_t a[4][4];
#pragma unroll
            for (int mi = 0; mi < 4; mi++) {
                int row = wm * 64 + mi * 16 + (lane & 15);
                uint32_t addr = a_base +
                    (uint32_t)((row * PITCH + ks + ((lane >> 4) << 3)) * 2);
                asm volatile("ldmatrix.sync.aligned.m8n8.x4.shared.b16 {%0,%1,%2,%3}, [%4];"
                             : "=r"(a[mi][0]), "=r"(a[mi][1]), "=r"(a[mi][2]), "=r"(a[mi][3])
                             : "r"(addr));
            }
            uint32_t bf[4][2];
#pragma unroll
            for (int ni = 0; ni < 4; ni++) {
                int n = wn * 32 + ni * 8 + (lane >> 2);
                const __half* bp = Bst + n * PITCH + ks + ((lane & 3) << 1);
                bf[ni][0] = *reinterpret_cast<const uint32_t*>(bp);
                bf[ni][1] = *reinterpret_cast<const uint32_t*>(bp + 8);
            }
#pragma unroll
            for (int mi = 0; mi < 4; mi++)
#pragma unroll
                for (int ni = 0; ni < 4; ni++) {
                    asm volatile(
                        "mma.sync.aligned.m16n8k16.row.col.f32.f16.f16.f32 "
                        "{%0,%1,%2,%3}, {%4,%5,%6,%7}, {%8,%9}, {%0,%1,%2,%3};"
                        : "+f"(acc[mi][ni][0]), "+f"(acc[mi][ni][1]),
                          "+f"(acc[mi][ni][2]), "+f"(acc[mi][ni][3])
                        : "r"(a[mi][0]), "r"(a[mi][1]), "r"(a[mi][2]), "r"(a[mi][3]),
                          "r"(bf[ni][0]), "r"(bf[ni][1]));
                }
        }
    };

#pragma unroll
    for (int s = 0; s < STG - 1; s++) {
        if (s < KT) issue_load(s, s);
        else asm volatile("cp.async.commit_group;\n" ::: "memory");
    }

    for (int kt = 0; kt < KT; kt++) {
        asm volatile("cp.async.wait_group %0;\n" :: "n"(STG - 2));
        __syncthreads();
        int nk = kt + STG - 1;
        if (nk < KT) issue_load(nk & (STG - 1), nk);
        else asm volatile("cp.async.commit_group;\n" ::: "memory");
        compute(kt & (STG - 1));
        __syncthreads();
    }

    // ---- epilogue ----
    int g = lane >> 2, q = lane & 3;
    long long cz32 = (long long)z * sC;
#pragma unroll
    for (int mi = 0; mi < 4; mi++) {
#pragma unroll
        for (int ni = 0; ni < 4; ni++) {
            int col = bn + wn * 32 + ni * 8 + 2 * q;
            if (col >= N) continue;
            float bb0 = bias ? bias[col]     : 0.f;
            float bb1 = bias ? bias[col + 1] : 0.f;
#pragma unroll
            for (int half_ = 0; half_ < 2; half_++) {
                int r = bm + wm * 64 + mi * 16 + g + half_ * 8;
                long long off = cz32 + (long long)r * ldc + col;
                float v0 = acc[mi][ni][half_ * 2 + 0] * alpha + bb0;
                float v1 = acc[mi][ni][half_ * 2 + 1] * alpha + bb1;
                if (act == 1) { v0 = fmaxf(v0, 0.f); v1 = fmaxf(v1, 0.f); }
                else if (act == 2) {
                    v0 = v0 > 0.f ? v0 : (expf(v0) - 1.f);
                    v1 = v1 > 0.f ? v1 : (expf(v1) - 1.f);
                } else if (act == 3) {
                    v0 = fmaxf(v0, 0.f); v1 = fmaxf(v1, 0.f);
                    float2 e = *reinterpret_cast<const float2*>(Eaux + off);
                    float g0 = 1.f / (1.f + expf(-e.x));
                    float g1 = 1.f / (1.f + expf(-e.y));
                    v0 = g0 * v0 + (1.f - g0) * e.x;
                    v1 = g1 * v1 + (1.f - g1) * e.y;
                } else if (act == 4) {
                    float2 e = *reinterpret_cast<const float2*>(Eaux + off);
                    float g0 = 0.6f / (1.f + expf(-v0));
                    float g1 = 0.6f / (1.f + expf(-v1));
                    v0 = (1.f - g0) * e.x + g0 * v0;
                    v1 = (1.f - g1) * e.y + g1 * v1;
                }
                if (C32) {
                    float2 o; o.x = v0; o.y = v1;
                    *reinterpret_cast<float2*>(C32 + off) = o;
                }
                if (C16) {
                    __half2 h = __floats2half2_rn(v0, v1);
                    *reinterpret_cast<__half2*>(C16 + off) = h;
                }
            }
        }
    }
}

// elementwise fp32 -> fp16 (n % 4 == 0)
__global__ void conv16(const float* __restrict__ in, __half* __restrict__ out, int n4)
{
    int i = blockIdx.x * blockDim.x + threadIdx.x;
    int stride = gridDim.x * blockDim.x;
    for (; i < n4; i += stride) {
        float4 v = reinterpret_cast<const float4*>(in)[i];
        __half2 h0 = __floats2half2_rn(v.x, v.y);
        __half2 h1 = __floats2half2_rn(v.z, v.w);
        reinterpret_cast<__half2*>(out)[2 * i]     = h0;
        reinterpret_cast<__half2*>(out)[2 * i + 1] = h1;
    }
}

// batched transpose + convert: out[b][c][r] = (half) in[b][r][c]
__global__ void convT16(const float* __restrict__ in, __half* __restrict__ out,
                        int R, int Cc)
{
    __shared__ float t[32][33];
    long long bo = (long long)blockIdx.z * R * Cc;
    const float* ib = in + bo;
    __half* ob = out + bo;
    int c0 = blockIdx.x << 5, r0 = blockIdx.y << 5;
    int tx = threadIdx.x, ty = threadIdx.y;
#pragma unroll
    for (int j = ty; j < 32; j += 8)
        t[j][tx] = ib[(long long)(r0 + j) * Cc + c0 + tx];
    __syncthreads();
#pragma unroll
    for (int j = ty; j < 32; j += 8)
        ob[(long long)(c0 + j) * R + r0 + tx] = __float2half_rn(t[tx][j]);
}

// fp32 batched transpose (for C21 = C12^T)
__global__ void transpose_bat(const float* __restrict__ in, float* __restrict__ out,
                              int R, int Cc)
{
    __shared__ float t[32][33];
    long long bo = (long long)blockIdx.z * R * Cc;
    const float* ib = in + bo;
    float* ob = out + bo;
    int c0 = blockIdx.x << 5, r0 = blockIdx.y << 5;
    int tx = threadIdx.x, ty = threadIdx.y;
#pragma unroll
    for (int j = ty; j < 32; j += 8)
        t[j][tx] = ib[(long long)(r0 + j) * Cc + c0 + tx];
    __syncthreads();
#pragma unroll
    for (int j = ty; j < 32; j += 8)
        ob[(long long)(c0 + j) * R + r0 + tx] = t[tx][j];
}

// =============================================================================
// Masked softmax over keys + mean over heads + diag->1 + row mask -> fp16 adj.
// One warp per head. grid=(S,B), block=256.
// =============================================================================
__global__ void softmax_mean_kernel(const float* __restrict__ scores,
                                    const int* __restrict__ attn_mask,
                                    __half* __restrict__ adj)
{
    int s = blockIdx.x, b = blockIdx.y;
    int tid = threadIdx.x;
    int lane = tid & 31, h = tid >> 5;
    __shared__ float accs[512];

    accs[tid] = 0.f; accs[tid + 256] = 0.f;
    __syncthreads();

    const float* row = scores + ((((long long)b * H_ + h) * S_ + s) << 9);
    const int* cm = attn_mask + b * S_;

    float v[16];
    float mx = -INFINITY;
#pragma unroll
    for (int j = 0; j < 16; j++) {
        int c = lane + (j << 5);
        float x = row[c];
        if (cm[c] == 0) x = -10000.f;
        v[j] = x;
        mx = fmaxf(mx, x);
    }
#pragma unroll
    for (int o = 16; o > 0; o >>= 1) mx = fmaxf(mx, __shfl_xor_sync(0xffffffffu, mx, o));

    float sum = 0.f;
#pragma unroll
    for (int j = 0; j < 16; j++) { v[j] = expf(v[j] - mx); sum += v[j]; }
#pragma unroll
    for (int o = 16; o > 0; o >>= 1) sum += __shfl_xor_sync(0xffffffffu, sum, o);
    float inv = 1.f / sum;

#pragma unroll
    for (int j = 0; j < 16; j++) atomicAdd(&accs[lane + (j << 5)], v[j] * inv);
    __syncthreads();

    float rmask = (float)attn_mask[b * S_ + s];
    long long obase = (((long long)b * S_ + s) << 9);
#pragma unroll
    for (int k = 0; k < 2; k++) {
        int c = tid + (k << 8);
        float val = (c == s) ? 1.f : accs[c] * 0.125f;
        adj[obase + c] = __float2half_rn(val * rmask);
    }
}

// Row L2-normalize -> fp16. One warp per row.
__global__ void normalize_kernel(const float* __restrict__ z, __half* __restrict__ out,
                                 int rows, int cols)
{
    int gw = (blockIdx.x * blockDim.x + threadIdx.x) >> 5;
    int lane = threadIdx.x & 31;
    int nw = (gridDim.x * blockDim.x) >> 5;
    for (int r = gw; r < rows; r += nw) {
        const float* zr = z + (long long)r * cols;
        float ss = 0.f;
        for (int c = lane; c < cols; c += 32) { float v = zr[c]; ss += v * v; }
#pragma unroll
        for (int o = 16; o > 0; o >>= 1) ss += __shfl_xor_sync(0xffffffffu, ss, o);
        float inv = 1.f / fmaxf(sqrtf(ss), 1e-12f);
        __half* orow = out + (long long)r * cols;
        for (int c = lane; c < cols; c += 32)
            orow[c] = __float2half_rn(zr[c] * inv);
    }
}

// =============================================================================
// Scope contrastive loss per (b,s). block=(512), grid=(S,B).
// =============================================================================
__global__ void loss_kernel(const float* __restrict__ C11, const float* __restrict__ C12,
                            const float* __restrict__ C21, const float* __restrict__ C22,
                            const int* __restrict__ s_mask, const int* __restrict__ a_mask,
                            float* __restrict__ rowloss)
{
    int s = blockIdx.x, b = blockIdx.y;
    int t = threadIdx.x;
    int lane = t & 31, wid = t >> 5;
    __shared__ float red8[8][16];
    __shared__ float Ssh[8];

    const float it = 1.f / 0.07f;
    long long base = (((long long)b * S_ + s) << 9);
    long long diag = base + s;

    float a   = (float)a_mask[b * S_ + s];
    float sms = (float)s_mask[b * S_ + s];
    float smt = (float)s_mask[b * S_ + t];

    float d11 = C11[diag], d12 = C12[diag], d21 = C21[diag], d22 = C22[diag];
    float dw1 = a * sms * d12;
    float dw2 = a * sms * d21;

    float c11 = C11[base + t], c12 = C12[base + t];
    float c21 = C21[base + t], c22 = C22[base + t];

    float vals[8];
    vals[0] = expf(a * c11 * it);
    vals[1] = expf(a * c12 * it);
    vals[2] = expf(a * smt * c11 * it);
    vals[3] = expf(a * smt * c12 * dw1 * it);
    vals[4] = expf(a * c22 * it);
    vals[5] = expf(a * c21 * it);
    vals[6] = expf(a * smt * c22 * it);
    vals[7] = expf(a * smt * c21 * dw2 * it);

#pragma unroll
    for (int k = 0; k < 8; k++) {
        float v = vals[k];
#pragma unroll
        for (int o = 16; o > 0; o >>= 1) v += __shfl_xor_sync(0xffffffffu, v, o);
        if (lane == 0) red8[k][wid] = v;
    }
    __syncthreads();
    if (t < 8) {
        float x = 0.f;
        for (int w2 = 0; w2 < 16; w2++) x += red8[t][w2];
        Ssh[t] = x;
    }
    __syncthreads();

    if (t == 0) {
        float pos1 = expf(a * sms * d12 * it)
                   + (Ssh[2] - expf(a * sms * d11 * it))
                   + (Ssh[3] - expf(dw1 * dw1 * it));
        float alle1 = Ssh[0] + Ssh[1] - expf(a * d11 * it);
        float l1v = -logf(pos1 / alle1);

        float pos2 = expf(a * sms * d21 * it)
                   + (Ssh[6] - expf(a * sms * d22 * it))
                   + (Ssh[7] - expf(dw2 * dw2 * it));
        float alle2 = Ssh[4] + Ssh[5] - expf(a * d22 * it);
        float l2v = -logf(pos2 / alle2);

        rowloss[b * S_ + s] = 0.5f * (l1v + l2v);
    }
}

__global__ void final_reduce_kernel(const float* __restrict__ rl, float* __restrict__ out)
{
    __shared__ float red[32];
    int tid = threadIdx.x;
    float s = 0.f;
    for (int i = tid; i < BS_; i += 1024) s += rl[i];
#pragma unroll
    for (int o = 16; o > 0; o >>= 1) s += __shfl_xor_sync(0xffffffffu, s, o);
    if ((tid & 31) == 0) red[tid >> 5] = s;
    __syncthreads();
    if (tid < 32) {
        float x = red[tid];
#pragma unroll
        for (int o = 16; o > 0; o >>= 1) x += __shfl_xor_sync(0xffffffffu, x, o);
        if (tid == 0) out[0] = x / (float)BS_;
    }
}

// =============================================================================
extern "C" void kernel_launch(void* const* d_in, const int* in_sizes, int n_in,
                              void* d_out, int out_size)
{
    const float* X     = (const float*)d_in[0];
    const float* adjm  = (const float*)d_in[1];
    const int*   amask = (const int*)d_in[2];
    const int*   smsk  = (const int*)d_in[3];
    const int*   amsk  = (const int*)d_in[4];
    const float* Wq    = (const float*)d_in[5];
    const float* bq    = (const float*)d_in[6];
    const float* Wk    = (const float*)d_in[7];
    const float* bk    = (const float*)d_in[8];
    const float* semW0 = (const float*)d_in[9];
    const float* semb0 = (const float*)d_in[10];
    const float* semW1 = (const float*)d_in[11];
    const float* semb1 = (const float*)d_in[12];
    const float* depW0 = (const float*)d_in[13];
    const float* depb0 = (const float*)d_in[14];
    const float* depW1 = (const float*)d_in[15];
    const float* depb1 = (const float*)d_in[16];
    const float* fc1W  = (const float*)d_in[17];
    const float* fc1b  = (const float*)d_in[18];
    const float* fc2W  = (const float*)d_in[19];
    const float* fc2b  = (const float*)d_in[20];
    const float* fc3W  = (const float*)d_in[21];
    const float* fc3b  = (const float*)d_in[22];
    const float* fc4W  = (const float*)d_in[23];
    const float* fc4b  = (const float*)d_in[24];
    float* out = (float*)d_out;

    cudaFuncSetAttribute(gemm_f16, cudaFuncAttributeMaxDynamicSharedMemorySize, GSMEM);

    float *pS, *pIsem, *pHl, *ph1, *ph2, *pRL;
    __half *Xh, *XTh, *adjmh, *Qh, *Kh, *adjh, *AH1h, *AH2h, *Isemh, *Icomh,
           *Hlh, *HTh, *Th, *n1h, *n2h,
           *WqT, *WkT, *sW0T, *dW0T, *fc4T, *sW1T, *dW1T, *fc3T, *fc1T, *fc2T;
    cudaGetSymbolAddress((void**)&pS, g_scores);
    cudaGetSymbolAddress((void**)&pIsem, g_Isem);
    cudaGetSymbolAddress((void**)&pHl, g_Hl);
    cudaGetSymbolAddress((void**)&ph1, g_h1);
    cudaGetSymbolAddress((void**)&ph2, g_h2);
    cudaGetSymbolAddress((void**)&pRL, g_rowloss);
    cudaGetSymbolAddress((void**)&Xh, g_Xh);
    cudaGetSymbolAddress((void**)&XTh, g_XTh);
    cudaGetSymbolAddress((void**)&adjmh, g_adjmh);
    cudaGetSymbolAddress((void**)&Qh, g_Qh);
    cudaGetSymbolAddress((void**)&Kh, g_Kh);
    cudaGetSymbolAddress((void**)&adjh, g_adjh);
    cudaGetSymbolAddress((void**)&AH1h, g_AH1h);
    cudaGetSymbolAddress((void**)&AH2h, g_AH2h);
    cudaGetSymbolAddress((void**)&Isemh, g_Isemh);
    cudaGetSymbolAddress((void**)&Icomh, g_Icomh);
    cudaGetSymbolAddress((void**)&Hlh, g_Hlh);
    cudaGetSymbolAddress((void**)&HTh, g_HTh);
    cudaGetSymbolAddress((void**)&Th, g_Th);
    cudaGetSymbolAddress((void**)&n1h, g_n1h);
    cudaGetSymbolAddress((void**)&n2h, g_n2h);
    cudaGetSymbolAddress((void**)&WqT, g_WqT);
    cudaGetSymbolAddress((void**)&WkT, g_WkT);
    cudaGetSymbolAddress((void**)&sW0T, g_sW0T);
    cudaGetSymbolAddress((void**)&dW0T, g_dW0T);
    cudaGetSymbolAddress((void**)&fc4T, g_fc4T);
    cudaGetSymbolAddress((void**)&sW1T, g_sW1T);
    cudaGetSymbolAddress((void**)&dW1T, g_dW1T);
    cudaGetSymbolAddress((void**)&fc3T, g_fc3T);
    cudaGetSymbolAddress((void**)&fc1T, g_fc1T);
    cudaGetSymbolAddress((void**)&fc2T, g_fc2T);

    float* C11 = pS;
    float* C12 = pS + (long long)B_ * S_ * S_;
    float* C21 = pS + 2LL * B_ * S_ * S_;
    float* C22 = pS + 3LL * B_ * S_ * S_;

    const long long SS = (long long)S_ * S_;
    const long long SD = (long long)S_ * D_;
    const long long SM = (long long)S_ * M_;
    dim3 tb(32, 8);

    // ---- conversions + transposed fp16 weights ----
    conv16<<<4096, 256>>>(X, Xh, BS_ * D_ / 4);
    conv16<<<4096, 256>>>(adjm, adjmh, B_ * S_ * S_ / 4);
    convT16<<<dim3(24, 16, B_), tb>>>(X, XTh, S_, D_);       // [B][D][S]
    convT16<<<dim3(24, 24, 1), tb>>>(Wq, WqT, D_, D_);
    convT16<<<dim3(24, 24, 1), tb>>>(Wk, WkT, D_, D_);
    convT16<<<dim3(12, 24, 1), tb>>>(semW0, sW0T, D_, M_);   // [M][D]
    convT16<<<dim3(12, 24, 1), tb>>>(depW0, dW0T, D_, M_);
    convT16<<<dim3(12, 24, 1), tb>>>(fc4W, fc4T, D_, M_);
    convT16<<<dim3(12, 12, 1), tb>>>(semW1, sW1T, M_, M_);
    convT16<<<dim3(12, 12, 1), tb>>>(depW1, dW1T, M_, M_);
    convT16<<<dim3(12, 12, 1), tb>>>(fc3W, fc3T, M_, M_);
    convT16<<<dim3(1, 12, 1), tb>>>(fc1W, fc1T, M_, 32);     // [32][M]
    convT16<<<dim3(12, 1, 1), tb>>>(fc2W, fc2T, 32, M_);     // [M][32]

    // ---- Q/K projections (fp16 out only) ----
    gemm_f16<<<dim3(6, 128, 1), 256, GSMEM>>>(Xh, WqT, bq, nullptr, Qh, nullptr,
        D_, D_, D_, D_, D_, 1, 0, 0, 0, 0, 0, 1.f, 0);
    gemm_f16<<<dim3(6, 128, 1), 256, GSMEM>>>(Xh, WkT, bk, nullptr, Kh, nullptr,
        D_, D_, D_, D_, D_, 1, 0, 0, 0, 0, 0, 1.f, 0);

    // ---- per-head scores (fp32 out) ----
    float alpha = 1.0f / sqrtf((float)DK_);
    gemm_f16<<<dim3(4, 4, B_ * H_), 256, GSMEM>>>(Qh, Kh, nullptr, pS, nullptr, nullptr,
        DK_, D_, D_, S_, S_, H_, SD, DK_, SD, DK_, SS, alpha, 0);

    // ---- masked softmax + head mean + diag/row-mask -> fp16 adj ----
    softmax_mean_kernel<<<dim3(S_, B_), 256>>>(pS, amask, adjh);

    // ---- Layer 0 ----
    gemm_f16<<<dim3(6, 4, B_), 256, GSMEM>>>(adjh, XTh, nullptr, nullptr, AH1h, nullptr,
        S_, S_, S_, D_, D_, 1, SS, 0, SD, 0, SD, 1.f, 0);
    gemm_f16<<<dim3(3, 128, 1), 256, GSMEM>>>(AH1h, sW0T, semb0, pIsem, Isemh, nullptr,
        D_, D_, D_, M_, M_, 1, 0, 0, 0, 0, 0, 1.f, 0);
    gemm_f16<<<dim3(6, 4, B_), 256, GSMEM>>>(adjmh, XTh, nullptr, nullptr, AH2h, nullptr,
        S_, S_, S_, D_, D_, 1, SS, 0, SD, 0, SD, 1.f, 0);
    gemm_f16<<<dim3(3, 128, 1), 256, GSMEM>>>(AH2h, dW0T, depb0, nullptr, Icomh, pIsem,
        D_, D_, D_, M_, M_, 1, 0, 0, 0, 0, 0, 1.f, 4);       // fused combine
    gemm_f16<<<dim3(3, 128, 1), 256, GSMEM>>>(Xh, fc4T, fc4b, pHl, nullptr, nullptr,
        D_, D_, D_, M_, M_, 1, 0, 0, 0, 0, 0, 1.f, 0);
    gemm_f16<<<dim3(3, 128, 1), 256, GSMEM>>>(Icomh, fc3T, fc3b, pHl, Hlh, pHl,
        M_, M_, M_, M_, M_, 1, 0, 0, 0, 0, 0, 1.f, 3);       // fused gate

    // ---- Hl^T fp16 per batch ----
    convT16<<<dim3(12, 16, B_), tb>>>(pHl, HTh, S_, M_);     // [B][M][S]

    // ---- Layer 1 ----
    gemm_f16<<<dim3(3, 4, B_), 256, GSMEM>>>(adjh, HTh, nullptr, nullptr, AH1h, nullptr,
        S_, S_, S_, M_, M_, 1, SS, 0, SM, 0, SM, 1.f, 0);
    gemm_f16<<<dim3(3, 128, 1), 256, GSMEM>>>(AH1h, sW1T, semb1, pIsem, Isemh, nullptr,
        M_, M_, M_, M_, M_, 1, 0, 0, 0, 0, 0, 1.f, 0);
    gemm_f16<<<dim3(3, 4, B_), 256, GSMEM>>>(adjmh, HTh, nullptr, nullptr, AH2h, nullptr,
        S_, S_, S_, M_, M_, 1, SS, 0, SM, 0, SM, 1.f, 0);
    gemm_f16<<<dim3(3, 128, 1), 256, GSMEM>>>(AH2h, dW1T, depb1, nullptr, Icomh, pIsem,
        M_, M_, M_, M_, M_, 1, 0, 0, 0, 0, 0, 1.f, 4);
    gemm_f16<<<dim3(3, 128, 1), 256, GSMEM>>>(Icomh, fc3T, fc3b, pHl, Hlh, pHl,
        M_, M_, M_, M_, M_, 1, 0, 0, 0, 0, 0, 1.f, 3);       // final H_l

    // ---- projection head ----
    gemm_f16<<<dim3(1, 128, 1), 256, GSMEM>>>(Hlh, fc1T, fc1b, nullptr, Th, nullptr,
        M_, M_, M_, 32, 32, 1, 0, 0, 0, 0, 0, 1.f, 2);
    gemm_f16<<<dim3(3, 128, 1), 256, GSMEM>>>(Th, fc2T, fc2b, ph1, nullptr, nullptr,
        32, 32, 32, M_, M_, 1, 0, 0, 0, 0, 0, 1.f, 0);
    gemm_f16<<<dim3(1, 128, 1), 256, GSMEM>>>(Isemh, fc1T, fc1b, nullptr, Th, nullptr,
        M_, M_, M_, 32, 32, 1, 0, 0, 0, 0, 0, 1.f, 2);
    gemm_f16<<<dim3(3, 128, 1), 256, GSMEM>>>(Th, fc2T, fc2b, ph2, nullptr, nullptr,
        32, 32, 32, M_, M_, 1, 0, 0, 0, 0, 0, 1.f, 0);

    // ---- normalize rows -> fp16 ----
    normalize_kernel<<<2048, 256>>>(ph1, n1h, BS_, M_);
    normalize_kernel<<<2048, 256>>>(ph2, n2h, BS_, M_);

    // ---- cosine similarity matrices: 3 GEMMs + 1 transpose ----
    gemm_f16<<<dim3(4, 4, B_), 256, GSMEM>>>(n1h, n1h, nullptr, C11, nullptr, nullptr,
        M_, M_, M_, S_, S_, 1, SM, 0, SM, 0, SS, 1.f, 0);
    gemm_f16<<<dim3(4, 4, B_), 256, GSMEM>>>(n1h, n2h, nullptr, C12, nullptr, nullptr,
        M_, M_, M_, S_, S_, 1, SM, 0, SM, 0, SS, 1.f, 0);
    gemm_f16<<<dim3(4, 4, B_), 256, GSMEM>>>(n2h, n2h, nullptr, C22, nullptr, nullptr,
        M_, M_, M_, S_, S_, 1, SM, 0, SM, 0, SS, 1.f, 0);
    transpose_bat<<<dim3(16, 16, B_), tb>>>(C12, C21, S_, S_);

    // ---- loss ----
    loss_kernel<<<dim3(S_, B_), 512>>>(C11, C12, C21, C22, smsk, amsk, pRL);
    final_reduce_kernel<<<1, 1024>>>(pRL, out);
}